// round 13
// baseline (speedup 1.0000x reference)
#include <cuda_runtime.h>
#include <cuda_bf16.h>
#include <cuda_fp16.h>
#include <math.h>
#include <stdint.h>

#define BATCH 8
#define NINST 100
#define NPAIR 9900
#define NCLS  51
#define NROWS (BATCH*NPAIR)   // 79200
#define NCAND 128
#define KC    64
#define MARGIN 2.5e-3f
// k2: 3 stages of 64KB (Ahi 16K | Alo 16K | B 32K), then smemL.
// W2 (64KB hi+lo) is loaded into stage-0's bytes after the mainloop.
#define K2A_LO 16384
#define K2B    32768
#define K2STG  65536
#define SMEML_OFF (3*K2STG)        // 196608
#define K2_SMEM   (SMEML_OFF + 128*65*4)   // 229888

// ---------------- scratch (device globals; no allocs allowed) ----------------
__device__ float  g_A12[BATCH*NINST*2048];
__device__ float  g_overall[NROWS];
__device__ float  g_predprob[NROWS];
__device__ float  g_margin[NROWS];
__device__ int    g_predlab[NROWS];
__device__ int    g_cand_idx[BATCH*NCAND];
__device__ int    g_cand_lab[BATCH*NCAND];
__device__ double g_cand_prob[BATCH*NCAND];
__device__ double g_cand_ovr[BATCH*NCAND];
__device__ int    g_fix_list[BATCH*NCAND];
__device__ int    g_fix_cnt[BATCH];
__device__ float  g_hs[2][BATCH*NCAND*1024];
__device__ float  g_hc[2][BATCH*NCAND*1024];
__device__ __align__(16) unsigned short g_Ahi[81100800];   // gathered phrase fp16 hi
__device__ __align__(16) unsigned short g_Alo[81100800];   // fp16 lo
__device__ __align__(16) unsigned short g_Bhi[1024*1024];  // W1c^T [n][k] fp16 hi
__device__ __align__(16) unsigned short g_W2fhi[64*1024];  // W2^T padded [64][1024] fp16 hi
__device__ __align__(16) unsigned short g_W2flo[64*1024];  // fp16 lo

// ---------------- helpers (baseline PTX only) ----------------
__device__ __forceinline__ uint32_t smem_u32(const void* p) {
    uint32_t a;
    asm("{ .reg .u64 t; cvta.to.shared.u64 t, %1; cvt.u32.u64 %0, t; }" : "=r"(a) : "l"(p));
    return a;
}
#define SWZ(x) ((x) ^ (((x) >> 3) & 0x70))
__device__ __forceinline__ void cpasync16(uint32_t dst, const void* src) {
    asm volatile("cp.async.cg.shared.global [%0], [%1], 16;" :: "r"(dst), "l"(src));
}
#define CP_COMMIT() asm volatile("cp.async.commit_group;" ::: "memory")
#define CP_WAIT(n)  asm volatile("cp.async.wait_group %0;" :: "n"(n) : "memory")
__device__ __forceinline__ void ldsm4(uint32_t* r, uint32_t addr) {
    asm volatile("ldmatrix.sync.aligned.m8n8.x4.shared.b16 {%0,%1,%2,%3}, [%4];"
        : "=r"(r[0]), "=r"(r[1]), "=r"(r[2]), "=r"(r[3]) : "r"(addr));
}
__device__ __forceinline__ void mma16816f(float* c, const uint32_t* a, const uint32_t* b) {
    asm volatile("mma.sync.aligned.m16n8k16.row.col.f32.f16.f16.f32 "
        "{%0,%1,%2,%3}, {%4,%5,%6,%7}, {%8,%9}, {%0,%1,%2,%3};"
        : "+f"(c[0]), "+f"(c[1]), "+f"(c[2]), "+f"(c[3])
        : "r"(a[0]), "r"(a[1]), "r"(a[2]), "r"(a[3]), "r"(b[0]), "r"(b[1]));
}
__device__ __forceinline__ uint32_t packh2(float x, float y) {
    __half2 t;
    t.x = __float2half_rn(x);
    t.y = __float2half_rn(y);
    return *(uint32_t*)&t;
}

// =============================================================================
// kprep_all: [blocks 0..1023] W1c -> g_Bhi (transposed fp16)
//            [blocks 1024..1087] W2 -> g_W2fhi/lo + init out_logits with b2
// =============================================================================
__global__ __launch_bounds__(256) void kprep_all(const float* __restrict__ W1,
                                                 const float* __restrict__ W2,
                                                 const float* __restrict__ b2,
                                                 float* __restrict__ out_logits)
{
    int bid = blockIdx.x;
    if (bid < 1024) {
        __shared__ float t[32][33];
        int kk0 = (bid & 31) * 32, nn0 = (bid >> 5) * 32;
        int tx = threadIdx.x & 31, ty = threadIdx.x >> 5;
        #pragma unroll
        for (int i = 0; i < 32; i += 8)
            t[ty + i][tx] = W1[(size_t)(2048 + kk0 + ty + i) * 1024 + nn0 + tx];
        __syncthreads();
        #pragma unroll
        for (int i = 0; i < 32; i += 8) {
            float x = t[tx][ty + i];
            size_t o = (size_t)(nn0 + ty + i) * 1024 + kk0 + tx;
            g_Bhi[o] = __half_as_ushort(__float2half_rn(x));
        }
    } else {
        int n = bid - 1024;     // 0..63
        for (int k = threadIdx.x; k < 1024; k += 256) {
            float x = (n < NCLS) ? W2[(size_t)k * NCLS + n] : 0.f;
            __half h = __float2half_rn(x);
            float lo = x - __half2float(h);
            g_W2fhi[n * 1024 + k] = __half_as_ushort(h);
            g_W2flo[n * 1024 + k] = __half_as_ushort(__float2half_rn(lo));
        }
        for (int i = n * 256 + threadIdx.x; i < NROWS * NCLS; i += 64 * 256)
            out_logits[i] = b2[i % NCLS];
    }
}

// =============================================================================
// prep_a: gather phrase rows per pair, split into fp16 hi/lo
// =============================================================================
__global__ __launch_bounds__(256) void kprep_a(const float* __restrict__ phrase,
                                               const int* __restrict__ pidx)
{
    int r = blockIdx.x;
    int b = r / NPAIR;
    int ph = pidx[r];
    const float4* src = (const float4*)(phrase + ((size_t)b * NPAIR + ph) * 1024);
    float4 v = src[threadIdx.x];
    ushort4 hi, lo;
    #define SPL(c, hf, lf) { __half _h = __float2half_rn(v.c); \
        float _l = v.c - __half2float(_h); \
        hf = __half_as_ushort(_h); lf = __half_as_ushort(__float2half_rn(_l)); }
    SPL(x, hi.x, lo.x) SPL(y, hi.y, lo.y) SPL(z, hi.z, lo.z) SPL(w, hi.w, lo.w)
    #undef SPL
    size_t o = (size_t)r * 1024 + threadIdx.x * 4;
    *(ushort4*)(g_Ahi + o) = hi;
    *(ushort4*)(g_Alo + o) = lo;
}

// =============================================================================
// K1: A12[r, j] = inst[r, :] @ W1[half*1024 + :, jc]   (fp32, small)
// =============================================================================
__global__ __launch_bounds__(256) void k1_instproj(const float* __restrict__ inst,
                                                   const float* __restrict__ W1)
{
    __shared__ float As[16][68];
    __shared__ float Bs[16][64];
    int tid = threadIdx.x;
    int n0 = blockIdx.x * 64;
    int m0 = blockIdx.y * 64;
    int half = n0 >> 10;
    int jc0  = n0 & 1023;
    const float* wbase = W1 + (size_t)half * 1024 * 1024 + jc0;

    int arow = tid >> 2;
    int akq  = (tid & 3) * 4;
    int ar   = m0 + arow; if (ar > 799) ar = 799;
    const float* aptr = inst + (size_t)ar * 1024 + akq;
    int brow = tid >> 4;
    int bn   = (tid & 15) * 4;
    int tx = tid & 15, ty = tid >> 4;
    float acc[4][4] = {};

    for (int k0 = 0; k0 < 1024; k0 += 16) {
        float4 av = *(const float4*)(aptr + k0);
        float4 bv = *(const float4*)(wbase + (size_t)(k0 + brow) * 1024 + bn);
        As[akq+0][arow] = av.x; As[akq+1][arow] = av.y;
        As[akq+2][arow] = av.z; As[akq+3][arow] = av.w;
        *(float4*)&Bs[brow][bn] = bv;
        __syncthreads();
        #pragma unroll
        for (int kk = 0; kk < 16; kk++) {
            float af[4], bf[4];
            *(float4*)af = *(const float4*)&As[kk][ty*4];
            *(float4*)bf = *(const float4*)&Bs[kk][tx*4];
            #pragma unroll
            for (int i = 0; i < 4; i++)
                #pragma unroll
                for (int j = 0; j < 4; j++)
                    acc[i][j] += af[i] * bf[j];
        }
        __syncthreads();
    }
    #pragma unroll
    for (int i = 0; i < 4; i++) {
        int r = m0 + ty*4 + i;
        if (r < 800)
            *(float4*)&g_A12[(size_t)r*2048 + n0 + tx*4] =
                make_float4(acc[i][0], acc[i][1], acc[i][2], acc[i][3]);
    }
}

// =============================================================================
// K2 v6 (fused, 3-stage pipeline, 1 barrier/chunk):
// h = lrelu(A@W1c + A12 gathers + b1); logits += h@W2 (FA2 pack, smem atomics).
// CTA 128 rows x 256 h-cols, 512 threads (4M x 4N warps).
// =============================================================================
__device__ __forceinline__ void k2_load(uint32_t st, int tid, int k0,
                                        size_t rowbase, int p0, int n0)
{
    #pragma unroll 1
    for (int i = tid; i < 4096; i += 512) {
        int q = i & 7;
        const unsigned short* src;
        uint32_t dst;
        if (i < 2048) {
            int t = i >> 10;
            int r = (i >> 3) & 127;
            int p = p0 + r; if (p > NPAIR - 1) p = NPAIR - 1;
            src = (t ? g_Alo : g_Ahi) + (rowbase + p) * 1024 + k0 + q * 8;
            dst = st + t * K2A_LO + SWZ(r * 128 + q * 16);
        } else {
            int j = i - 2048;
            int n = (j >> 3) & 255;
            src = g_Bhi + (size_t)(n0 + n) * 1024 + k0 + q * 8;
            dst = st + K2B + SWZ(n * 128 + q * 16);
        }
        cpasync16(dst, src);
    }
}

__global__ void __launch_bounds__(512, 1) k2_mma(const float* __restrict__ b1,
                                                 const int* __restrict__ connect,
                                                 float* __restrict__ out_logits)
{
    extern __shared__ __align__(1024) char smem[];
    uint32_t sb = smem_u32(smem);
    int tid = threadIdx.x;
    int lane = tid & 31, wid = tid >> 5;
    int wm = wid & 3, wn = wid >> 2;       // 4 M-warps x 4 N-warps
    int n0 = blockIdx.x * 256;
    int p0 = blockIdx.y * 128;
    int b  = blockIdx.z;
    size_t rowbase = (size_t)b * NPAIR;
    float* smemL = (float*)(smem + SMEML_OFF);

    // zero logits-reduce buffer (region untouched by stages)
    for (int i = tid; i < 128*65; i += 512) smemL[i] = 0.f;

    float acc[2][8][4] = {};

    // prologue: chunks 0,1,2 into stages 0,1,2
    k2_load(sb,           tid, 0,    rowbase, p0, n0); CP_COMMIT();
    k2_load(sb + K2STG,   tid, KC,   rowbase, p0, n0); CP_COMMIT();
    k2_load(sb + 2*K2STG, tid, 2*KC, rowbase, p0, n0); CP_COMMIT();

    #pragma unroll 1
    for (int c = 0; c < 16; c++) {
        if (c == 0)      CP_WAIT(2);
        else if (c < 15) CP_WAIT(1);
        else             CP_WAIT(0);
        __syncthreads();   // chunk c visible; all threads done with chunk c-1

        // issue load for chunk c+2 into the stage freed by chunk c-1
        if (c >= 1 && c <= 13) {
            k2_load(sb + ((c + 2) % 3) * K2STG, tid, (c + 2) * KC, rowbase, p0, n0);
            CP_COMMIT();
        }

        uint32_t st  = sb + (c % 3) * K2STG;
        uint32_t sAh = st, sAl = st + K2A_LO, sBh = st + K2B;

        #pragma unroll
        for (int ks = 0; ks < 4; ks++) {
            int kb = ks * 32;
            uint32_t ah[2][4], al[2][4], bh[4][4];
            #pragma unroll
            for (int mt = 0; mt < 2; mt++) {
                uint32_t off = SWZ((wm*32 + mt*16 + (lane & 15)) * 128 + kb + (lane >> 4) * 16);
                ldsm4(ah[mt], sAh + off);
                ldsm4(al[mt], sAl + off);
            }
            int nrow  = (lane & 7) + ((lane >> 4) & 1) * 8;
            int khalf = ((lane >> 3) & 1) * 16;
            #pragma unroll
            for (int ntq = 0; ntq < 4; ntq++) {
                uint32_t off = SWZ((wn*64 + ntq*16 + nrow) * 128 + kb + khalf);
                ldsm4(bh[ntq], sBh + off);
            }
            #pragma unroll
            for (int mt = 0; mt < 2; mt++)
                #pragma unroll
                for (int nt = 0; nt < 8; nt++) {
                    const uint32_t* bhp = &bh[nt >> 1][(nt & 1) * 2];
                    mma16816f(acc[mt][nt], ah[mt], bhp);
                    mma16816f(acc[mt][nt], al[mt], bhp);
                }
        }
    }

    // all stage reads done -> reuse stage 0 bytes for W2 tiles
    __syncthreads();
    #pragma unroll 1
    for (int i = tid; i < 4096; i += 512) {
        int kind = i >> 11;
        int wnt  = (i >> 9) & 3;
        int n    = (i >> 3) & 63;
        int q    = i & 7;
        const unsigned short* src =
            (kind ? g_W2flo : g_W2fhi) + (size_t)n * 1024 + n0 + wnt * 64 + q * 8;
        uint32_t dst = sb + kind * 32768 + wnt * 8192 + SWZ(n * 128 + q * 16);
        cpasync16(dst, src);
    }
    CP_COMMIT();

    // ---- epilogue 1: gather-adds + lrelu into acc (register-only) ----
    int gp = lane >> 2, tq = lane & 3;
    int n0w = n0 + wn * 64;
    size_t bb2 = (size_t)b * 2 * NPAIR;
    const float* a12b = g_A12 + (size_t)b * NINST * 2048;
    #pragma unroll
    for (int mt = 0; mt < 2; mt++) {
        #pragma unroll
        for (int half = 0; half < 2; half++) {
            int p = p0 + wm*32 + mt*16 + gp + half*8;
            if (p >= NPAIR) continue;
            int sub = connect[bb2 + p];
            int obj = connect[bb2 + NPAIR + p];
            const float* r1 = a12b + (size_t)sub * 2048 + n0w;
            const float* r2 = a12b + (size_t)obj * 2048 + 1024 + n0w;
            #pragma unroll
            for (int nt = 0; nt < 8; nt++) {
                int cc = nt*8 + tq*2;
                float2 v1 = *(const float2*)(r1 + cc);
                float2 v2 = *(const float2*)(r2 + cc);
                float2 vb = *(const float2*)(b1 + n0w + cc);
                float x = acc[mt][nt][half*2+0] + v1.x + v2.x + vb.x;
                float y = acc[mt][nt][half*2+1] + v1.y + v2.y + vb.y;
                acc[mt][nt][half*2+0] = x > 0.f ? x : 0.01f * x;
                acc[mt][nt][half*2+1] = y > 0.f ? y : 0.01f * y;
            }
        }
    }

    // ---- epilogue 2: pack h into fp16 hi/lo A-fragments ----
    uint32_t ahf[2][4][4], alf[2][4][4];
    #pragma unroll
    for (int mt = 0; mt < 2; mt++)
        #pragma unroll
        for (int j = 0; j < 4; j++)
            #pragma unroll
            for (int q = 0; q < 4; q++) {
                int nt = 2*j + (q >> 1);
                int ci = (q & 1) * 2;
                float x = acc[mt][nt][ci], y = acc[mt][nt][ci+1];
                uint32_t hp = packh2(x, y);
                __half2 hh = *(__half2*)&hp;
                ahf[mt][j][q] = hp;
                alf[mt][j][q] = packh2(x - __half2float(hh.x), y - __half2float(hh.y));
            }

    CP_WAIT(0);
    __syncthreads();   // W2 tiles visible

    // ---- epilogue 3: mini-GEMM h(32x64) @ W2(64k x 64n), 3 products ----
    uint32_t w2h = sb + wn * 8192;
    uint32_t w2l = sb + 32768 + wn * 8192;
    int nrow  = (lane & 7) + ((lane >> 4) & 1) * 8;
    int khalf = ((lane >> 3) & 1) * 16;
    #pragma unroll
    for (int nh = 0; nh < 2; nh++) {
        float acc2[2][4][4] = {};
        #pragma unroll
        for (int j = 0; j < 4; j++) {
            int kb = j * 32;
            uint32_t bh[2][4], bl[2][4];
            #pragma unroll
            for (int ntq = 0; ntq < 2; ntq++) {
                uint32_t off = SWZ((nh*32 + ntq*16 + nrow) * 128 + kb + khalf);
                ldsm4(bh[ntq], w2h + off);
                ldsm4(bl[ntq], w2l + off);
            }
            #pragma unroll
            for (int mt = 0; mt < 2; mt++)
                #pragma unroll
                for (int nt = 0; nt < 4; nt++) {
                    const uint32_t* bhp = &bh[nt >> 1][(nt & 1) * 2];
                    const uint32_t* blp = &bl[nt >> 1][(nt & 1) * 2];
                    mma16816f(acc2[mt][nt], ahf[mt][j], bhp);
                    mma16816f(acc2[mt][nt], alf[mt][j], bhp);
                    mma16816f(acc2[mt][nt], ahf[mt][j], blp);
                }
        }
        // cross-warp reduce via smem atomics (no serialization barriers)
        #pragma unroll
        for (int mt = 0; mt < 2; mt++)
            #pragma unroll
            for (int nt = 0; nt < 4; nt++)
                #pragma unroll
                for (int ci = 0; ci < 4; ci++) {
                    int row = wm*32 + mt*16 + gp + (ci >> 1) * 8;
                    int col = nh*32 + nt*8 + tq*2 + (ci & 1);
                    atomicAdd(&smemL[row*65 + col], acc2[mt][nt][ci]);
                }
    }
    __syncthreads();

    // ---- epilogue 4: REDG partial logits into global ----
    #pragma unroll 1
    for (int i = tid; i < 128*64; i += 512) {
        int row = i >> 6, col = i & 63;
        int p = p0 + row;
        if (p < NPAIR && col < NCLS)
            atomicAdd(&out_logits[((size_t)b*NPAIR + p)*NCLS + col], smemL[row*65 + col]);
    }
}

// =============================================================================
// K3b: softmax -> probs; dense decisions + margins
// =============================================================================
__global__ void k3b_softmax(const float* __restrict__ out_logits,
                            const float* __restrict__ scores,
                            const int*   __restrict__ connect,
                            float* __restrict__ out_probs)
{
    int row = blockIdx.x * blockDim.x + threadIdx.x;
    if (row >= NROWS) return;
    const float* lp = out_logits + (size_t)row * NCLS;
    float l[NCLS];
    float m = -1e30f;
    #pragma unroll
    for (int c = 0; c < NCLS; c++) { l[c] = lp[c]; m = fmaxf(m, l[c]); }
    float s = 0.f;
    #pragma unroll
    for (int c = 0; c < NCLS; c++) { l[c] = expf(l[c] - m); s += l[c]; }
    float inv = 1.0f / s;
    float* pp = out_probs + (size_t)row * NCLS;
    float best = 0.f, second = 0.f; int bidx = 0;
    #pragma unroll
    for (int c = 0; c < NCLS; c++) {
        float pr = l[c] * inv;
        pp[c] = pr;
        if (c >= 1) {
            if (pr > best) { second = best; best = pr; bidx = c; }
            else if (pr > second) second = pr;
        }
    }
    int b = row / NPAIR, p = row % NPAIR;
    int si = connect[(size_t)b*2*NPAIR + p];
    int oi = connect[(size_t)b*2*NPAIR + NPAIR + p];
    g_overall[row]  = best * scores[b*NINST + si] * scores[b*NINST + oi];
    g_predprob[row] = best;
    g_predlab[row]  = bidx;
    g_margin[row]   = best - second;
}

// =============================================================================
// K4: warp-tournament top-NCAND selection
// =============================================================================
__global__ __launch_bounds__(1024) void k4_select()
{
    __shared__ float vals[NPAIR];
    __shared__ float wmax[32];
    __shared__ int   warg[32];
    __shared__ int   s_win;
    int b = blockIdx.x, tid = threadIdx.x, w = tid >> 5, lane = tid & 31;
    for (int i = tid; i < NPAIR; i += 1024) vals[i] = g_overall[b*NPAIR + i];
    __syncthreads();

    int lo = w * 310;
    int hiv = lo + 310; if (hiv > NPAIR) hiv = NPAIR;
    float bv = -1.f; int bi = 0x7fffffff;
    for (int i = lo + lane; i < hiv; i += 32) {
        float v = vals[i];
        if (v > bv || (v == bv && i < bi)) { bv = v; bi = i; }
    }
    #pragma unroll
    for (int o = 16; o; o >>= 1) {
        float ov = __shfl_down_sync(0xffffffffu, bv, o);
        int   oi = __shfl_down_sync(0xffffffffu, bi, o);
        if (ov > bv || (ov == bv && oi < bi)) { bv = ov; bi = oi; }
    }
    if (lane == 0) { wmax[w] = bv; warg[w] = bi; }
    __syncthreads();

    for (int t = 0; t < NCAND; t++) {
        if (tid < 32) {
            float v = wmax[lane]; int i2 = warg[lane];
            #pragma unroll
            for (int o = 16; o; o >>= 1) {
                float ov = __shfl_down_sync(0xffffffffu, v, o);
                int   oi = __shfl_down_sync(0xffffffffu, i2, o);
                if (ov > v || (ov == v && oi < i2)) { v = ov; i2 = oi; }
            }
            if (lane == 0) {
                g_cand_idx[b*NCAND + t] = i2;
                vals[i2] = -2.f;
                s_win = i2 / 310;
            }
        }
        __syncthreads();
        if (w == s_win) {
            float nv = -1.f; int ni = 0x7fffffff;
            for (int i = lo + lane; i < hiv; i += 32) {
                float v = vals[i];
                if (v > nv || (v == nv && i < ni)) { nv = v; ni = i; }
            }
            #pragma unroll
            for (int o = 16; o; o >>= 1) {
                float ov = __shfl_down_sync(0xffffffffu, nv, o);
                int   oi = __shfl_down_sync(0xffffffffu, ni, o);
                if (ov > nv || (ov == nv && oi < ni)) { nv = ov; ni = oi; }
            }
            if (lane == 0) { wmax[w] = nv; warg[w] = ni; }
        }
        __syncthreads();
    }
}

// =============================================================================
// K4b: init candidate outputs with dense values; flag decision-critical ones
// =============================================================================
__global__ __launch_bounds__(NCAND) void k4b_flag()
{
    __shared__ float ov[NCAND];
    __shared__ int   fl[NCAND];
    int b = blockIdx.x, i = threadIdx.x;
    int cand = g_cand_idx[b*NCAND + i];
    int row  = b*NPAIR + cand;
    float o  = g_overall[row];
    ov[i] = o;
    __syncthreads();

    int f = (g_margin[row] < MARGIN) ? 1 : 0;
    for (int j = 0; j < NCAND; j++)
        if (j != i && fabsf(o - ov[j]) < MARGIN) f = 1;
    fl[i] = f;

    g_cand_ovr [b*NCAND + i] = (double)o;
    g_cand_prob[b*NCAND + i] = (double)g_predprob[row];
    g_cand_lab [b*NCAND + i] = g_predlab[row];
    __syncthreads();

    if (i == 0) {
        int n = 0;
        for (int j = 0; j < NCAND; j++)
            if (fl[j]) g_fix_list[b*NCAND + (n++)] = j;
        g_fix_cnt[b] = n;
    }
}

// =============================================================================
// K5: compensated-fp32 exact partial h — FLAGGED candidates only
// =============================================================================
#define CPB 4
__global__ __launch_bounds__(256) void k5_repair_h(const float* __restrict__ inst,
                                                   const float* __restrict__ phrase,
                                                   const float* __restrict__ W1,
                                                   const int*   __restrict__ connect,
                                                   const int*   __restrict__ pidx)
{
    __shared__ float sf[CPB][1536];
    int ks = blockIdx.x;
    int g  = blockIdx.y;
    int b  = blockIdx.z;
    int tid = threadIdx.x;
    int k0 = ks * 1536;

    int cnt = g_fix_cnt[b];
    if (g * CPB >= cnt) return;
    int slots[CPB];

    #pragma unroll 1
    for (int c = 0; c < CPB; c++) {
        int jj = g*CPB + c; if (jj > cnt - 1) jj = cnt - 1;
        int slot = b*NCAND + g_fix_list[b*NCAND + jj];
        slots[c] = slot;
        int p  = g_cand_idx[slot];
        int si = connect[(size_t)b*2*NPAIR + p];
        int oi = connect[(size_t)b*2*NPAIR + NPAIR + p];
        int ph = pidx[b*NPAIR + p];
        const float* s0 = inst   + ((size_t)b*NINST + si)*1024;
        const float* s1 = inst   + ((size_t)b*NINST + oi)*1024;
        const float* s2 = phrase + ((size_t)b*NPAIR + ph)*1024;
        for (int k = tid; k < 1536; k += 256) {
            int f = k0 + k;
            float v;
            if (f < 1024)       v = s0[f];
            else if (f < 2048)  v = s1[f - 1024];
            else                v = s2[f - 2048];
            sf[c][k] = v;
        }
    }
    __syncthreads();

    float s[CPB][4] = {};
    float comp[CPB][4] = {};
    const float* wcol = W1 + (size_t)k0 * 1024 + tid * 4;
    #pragma unroll 2
    for (int k = 0; k < 1536; k++) {
        float4 w = *(const float4*)(wcol + (size_t)k * 1024);
        float wv[4] = {w.x, w.y, w.z, w.w};
        #pragma unroll
        for (int c = 0; c < CPB; c++) {
            float f = sf[c][k];
            #pragma unroll
            for (int j = 0; j < 4; j++) {
                float p  = __fmul_rn(f, wv[j]);
                float e  = __fmaf_rn(f, wv[j], -p);
                float t  = __fadd_rn(s[c][j], p);
                float z  = __fsub_rn(t, s[c][j]);
                float e2 = __fadd_rn(__fsub_rn(s[c][j], __fsub_rn(t, z)),
                                     __fsub_rn(p, z));
                comp[c][j] = __fadd_rn(comp[c][j], __fadd_rn(e2, e));
                s[c][j] = t;
            }
        }
    }
    float* outs = g_hs[ks];
    float* outc = g_hc[ks];
    #pragma unroll
    for (int c = 0; c < CPB; c++) {
        int slot = slots[c];
        *(float4*)(outs + (size_t)slot*1024 + tid*4) =
            make_float4(s[c][0], s[c][1], s[c][2], s[c][3]);
        *(float4*)(outc + (size_t)slot*1024 + tid*4) =
            make_float4(comp[c][0], comp[c][1], comp[c][2], comp[c][3]);
    }
}

// =============================================================================
// K6: exact decisions — FLAGGED candidates only
// =============================================================================
__global__ __launch_bounds__(64) void k6_decide(const float* __restrict__ W2,
                                                const float* __restrict__ b2,
                                                const float* __restrict__ b1,
                                                const float* __restrict__ scores,
                                                const int*   __restrict__ connect)
{
    __shared__ double sh[1024];
    __shared__ double slog[NCLS];
    int gid = blockIdx.x;
    int b = gid >> 7, j = gid & (NCAND - 1);
    if (j >= g_fix_cnt[b]) return;
    int slot = b*NCAND + g_fix_list[b*NCAND + j];
    int tid = threadIdx.x;
    size_t base = (size_t)slot * 1024;
    for (int k = tid; k < 1024; k += 64) {
        double v = ((double)g_hs[0][base + k] + (double)g_hc[0][base + k])
                 + ((double)g_hs[1][base + k] + (double)g_hc[1][base + k])
                 + (double)b1[k];
        v = v > 0.0 ? v : 0.01 * v;
        sh[k] = v;
    }
    __syncthreads();

    if (tid < NCLS) {
        double acc = 0.0;
        #pragma unroll 8
        for (int k = 0; k < 1024; k++)
            acc = fma(sh[k], (double)W2[(size_t)k*NCLS + tid], acc);
        slog[tid] = acc + (double)b2[tid];
    }
    __syncthreads();

    if (tid == 0) {
        double m = slog[0];
        for (int c = 1; c < NCLS; c++) m = slog[c] > m ? slog[c] : m;
        double e[NCLS]; double ssum = 0.0;
        for (int c = 0; c < NCLS; c++) { e[c] = exp(slog[c] - m); ssum += e[c]; }
        double best = 0.0; int bl = 0;
        for (int c = 1; c < NCLS; c++) {
            double pr = e[c] / ssum;
            if (pr > best) { best = pr; bl = c; }
        }
        int p = g_cand_idx[slot];
        int si = connect[(size_t)b*2*NPAIR + p];
        int oi = connect[(size_t)b*2*NPAIR + NPAIR + p];
        double ov = best * (double)scores[b*NINST + si] * (double)scores[b*NINST + oi];
        g_cand_ovr[slot]  = ov;
        g_cand_prob[slot] = best;
        g_cand_lab[slot]  = bl;
    }
}

// =============================================================================
// K7: final top-100 per batch over NCAND candidates
// =============================================================================
__global__ __launch_bounds__(128) void k7_final(float* __restrict__ outbase)
{
    __shared__ double v[NCAND];
    __shared__ int    pix[NCAND];
    int b = blockIdx.x, tid = threadIdx.x;
    v[tid]   = g_cand_ovr[b*NCAND + tid];
    pix[tid] = g_cand_idx[b*NCAND + tid];
    __syncthreads();

    if (tid == 0) {
        float* out_lab  = outbase;
        float* out_prob = outbase + 800;
        float* out_val  = outbase + 1600;
        float* out_idx  = outbase + 2400;
        for (int t = 0; t < 100; t++) {
            double bv = -1.0; int bj = 0; int bidx = 0x7fffffff;
            for (int j = 0; j < NCAND; j++) {
                double val = v[j]; int ix = pix[j];
                if (val > bv || (val == bv && ix < bidx)) { bv = val; bj = j; bidx = ix; }
            }
            int slot2 = b*NCAND + bj;
            out_val [b*100 + t] = (float)bv;
            out_idx [b*100 + t] = (float)bidx;
            out_lab [b*100 + t] = (float)g_cand_lab[slot2];
            out_prob[b*100 + t] = (float)g_cand_prob[slot2];
            v[bj] = -2.0;
        }
    }
}

// =============================================================================
extern "C" void kernel_launch(void* const* d_in, const int* in_sizes, int n_in,
                              void* d_out, int out_size)
{
    const float* inst    = (const float*)d_in[0];
    const float* phrase  = (const float*)d_in[1];
    const float* scores  = (const float*)d_in[2];
    const float* W1      = (const float*)d_in[3];
    const float* b1      = (const float*)d_in[4];
    const float* W2      = (const float*)d_in[5];
    const float* b2      = (const float*)d_in[6];
    const int*   connect = (const int*)d_in[7];
    const int*   pidx    = (const int*)d_in[8];

    float* out        = (float*)d_out;
    float* out_logits = out;
    float* out_probs  = out + (size_t)BATCH*NPAIR*NCLS;
    float* out_top    = out + (size_t)2*BATCH*NPAIR*NCLS;

    cudaFuncSetAttribute(k2_mma, cudaFuncAttributeMaxDynamicSharedMemorySize, K2_SMEM);

    // k2 is the 4th launch -> it lands in the ncu capture slot
    kprep_all<<<1088, 256>>>(W1, W2, b2, out_logits);
    kprep_a<<<NROWS, 256>>>(phrase, pidx);
    k1_instproj<<<dim3(32, 13), 256>>>(inst, W1);
    k2_mma<<<dim3(4, 78, BATCH), 512, K2_SMEM>>>(b1, connect, out_logits);
    k3b_softmax<<<(NROWS + 255) / 256, 256>>>(out_logits, scores, connect, out_probs);
    k4_select<<<BATCH, 1024>>>();
    k4b_flag<<<BATCH, NCAND>>>();
    k5_repair_h<<<dim3(2, 32, BATCH), 256>>>(inst, phrase, W1, connect, pidx);
    k6_decide<<<BATCH*NCAND, 64>>>(W2, b2, b1, scores, connect);
    k7_final<<<BATCH, 128>>>(out_top);
}

// round 14
// speedup vs baseline: 1.0481x; 1.0481x over previous
#include <cuda_runtime.h>
#include <cuda_bf16.h>
#include <cuda_fp16.h>
#include <math.h>
#include <stdint.h>

#define BATCH 8
#define NINST 100
#define NPAIR 9900
#define NCLS  51
#define NROWS (BATCH*NPAIR)   // 79200
#define NCAND 128
#define KC    64
#define MARGIN 2e-5f
// k2: 2 stages of 96KB (Ahi 16K | Alo 16K | Bhi 32K | Blo 32K), then smemL.
// W2 (64KB hi+lo) reuses stage-0 bytes after the mainloop.
#define K2A_LO 16384
#define K2B_HI 32768
#define K2B_LO 65536
#define K2STG  98304
#define SMEML_OFF (2*K2STG)                // 196608
#define K2_SMEM   (SMEML_OFF + 128*65*4)   // 229888

// ---------------- scratch (device globals; no allocs allowed) ----------------
__device__ float  g_A12[BATCH*NINST*2048];
__device__ float  g_overall[NROWS];
__device__ float  g_predprob[NROWS];
__device__ float  g_margin[NROWS];
__device__ int    g_predlab[NROWS];
__device__ int    g_cand_idx[BATCH*NCAND];
__device__ int    g_cand_lab[BATCH*NCAND];
__device__ double g_cand_prob[BATCH*NCAND];
__device__ double g_cand_ovr[BATCH*NCAND];
__device__ int    g_fix_list[BATCH*NCAND];
__device__ int    g_fix_cnt[BATCH];
__device__ float  g_hs[2][BATCH*NCAND*1024];
__device__ float  g_hc[2][BATCH*NCAND*1024];
__device__ __align__(16) unsigned short g_Ahi[81100800];   // gathered phrase fp16 hi
__device__ __align__(16) unsigned short g_Alo[81100800];   // fp16 lo
__device__ __align__(16) unsigned short g_Bhi[1024*1024];  // W1c^T [n][k] fp16 hi
__device__ __align__(16) unsigned short g_Blo[1024*1024];  // fp16 lo
__device__ __align__(16) unsigned short g_W2fhi[64*1024];  // W2^T padded fp16 hi
__device__ __align__(16) unsigned short g_W2flo[64*1024];  // fp16 lo

// ---------------- helpers (baseline PTX only) ----------------
__device__ __forceinline__ uint32_t smem_u32(const void* p) {
    uint32_t a;
    asm("{ .reg .u64 t; cvta.to.shared.u64 t, %1; cvt.u32.u64 %0, t; }" : "=r"(a) : "l"(p));
    return a;
}
#define SWZ(x) ((x) ^ (((x) >> 3) & 0x70))
__device__ __forceinline__ void cpasync16(uint32_t dst, const void* src) {
    asm volatile("cp.async.cg.shared.global [%0], [%1], 16;" :: "r"(dst), "l"(src));
}
#define CP_COMMIT() asm volatile("cp.async.commit_group;" ::: "memory")
#define CP_WAIT(n)  asm volatile("cp.async.wait_group %0;" :: "n"(n) : "memory")
__device__ __forceinline__ void ldsm4(uint32_t* r, uint32_t addr) {
    asm volatile("ldmatrix.sync.aligned.m8n8.x4.shared.b16 {%0,%1,%2,%3}, [%4];"
        : "=r"(r[0]), "=r"(r[1]), "=r"(r[2]), "=r"(r[3]) : "r"(addr));
}
__device__ __forceinline__ void mma16816f(float* c, const uint32_t* a, const uint32_t* b) {
    asm volatile("mma.sync.aligned.m16n8k16.row.col.f32.f16.f16.f32 "
        "{%0,%1,%2,%3}, {%4,%5,%6,%7}, {%8,%9}, {%0,%1,%2,%3};"
        : "+f"(c[0]), "+f"(c[1]), "+f"(c[2]), "+f"(c[3])
        : "r"(a[0]), "r"(a[1]), "r"(a[2]), "r"(a[3]), "r"(b[0]), "r"(b[1]));
}
__device__ __forceinline__ uint32_t packh2(float x, float y) {
    __half2 t;
    t.x = __float2half_rn(x);
    t.y = __float2half_rn(y);
    return *(uint32_t*)&t;
}

// =============================================================================
// kprep_all: [0..1023] W1c -> g_Bhi/g_Blo (transposed fp16 hi/lo)
//            [1024..1087] W2 -> g_W2fhi/lo + init out_logits with b2
// =============================================================================
__global__ __launch_bounds__(256) void kprep_all(const float* __restrict__ W1,
                                                 const float* __restrict__ W2,
                                                 const float* __restrict__ b2,
                                                 float* __restrict__ out_logits)
{
    int bid = blockIdx.x;
    if (bid < 1024) {
        __shared__ float t[32][33];
        int kk0 = (bid & 31) * 32, nn0 = (bid >> 5) * 32;
        int tx = threadIdx.x & 31, ty = threadIdx.x >> 5;
        #pragma unroll
        for (int i = 0; i < 32; i += 8)
            t[ty + i][tx] = W1[(size_t)(2048 + kk0 + ty + i) * 1024 + nn0 + tx];
        __syncthreads();
        #pragma unroll
        for (int i = 0; i < 32; i += 8) {
            float x = t[tx][ty + i];
            __half h = __float2half_rn(x);
            float lo = x - __half2float(h);
            size_t o = (size_t)(nn0 + ty + i) * 1024 + kk0 + tx;
            g_Bhi[o] = __half_as_ushort(h);
            g_Blo[o] = __half_as_ushort(__float2half_rn(lo));
        }
    } else {
        int n = bid - 1024;     // 0..63
        for (int k = threadIdx.x; k < 1024; k += 256) {
            float x = (n < NCLS) ? W2[(size_t)k * NCLS + n] : 0.f;
            __half h = __float2half_rn(x);
            float lo = x - __half2float(h);
            g_W2fhi[n * 1024 + k] = __half_as_ushort(h);
            g_W2flo[n * 1024 + k] = __half_as_ushort(__float2half_rn(lo));
        }
        for (int i = n * 256 + threadIdx.x; i < NROWS * NCLS; i += 64 * 256)
            out_logits[i] = b2[i % NCLS];
    }
}

// =============================================================================
// prep_a: gather phrase rows per pair, split into fp16 hi/lo
// =============================================================================
__global__ __launch_bounds__(256) void kprep_a(const float* __restrict__ phrase,
                                               const int* __restrict__ pidx)
{
    int r = blockIdx.x;
    int b = r / NPAIR;
    int ph = pidx[r];
    const float4* src = (const float4*)(phrase + ((size_t)b * NPAIR + ph) * 1024);
    float4 v = src[threadIdx.x];
    ushort4 hi, lo;
    #define SPL(c, hf, lf) { __half _h = __float2half_rn(v.c); \
        float _l = v.c - __half2float(_h); \
        hf = __half_as_ushort(_h); lf = __half_as_ushort(__float2half_rn(_l)); }
    SPL(x, hi.x, lo.x) SPL(y, hi.y, lo.y) SPL(z, hi.z, lo.z) SPL(w, hi.w, lo.w)
    #undef SPL
    size_t o = (size_t)r * 1024 + threadIdx.x * 4;
    *(ushort4*)(g_Ahi + o) = hi;
    *(ushort4*)(g_Alo + o) = lo;
}

// =============================================================================
// K1: A12[r, j] = inst[r, :] @ W1[half*1024 + :, jc]   (fp32, small)
// =============================================================================
__global__ __launch_bounds__(256) void k1_instproj(const float* __restrict__ inst,
                                                   const float* __restrict__ W1)
{
    __shared__ float As[16][68];
    __shared__ float Bs[16][64];
    int tid = threadIdx.x;
    int n0 = blockIdx.x * 64;
    int m0 = blockIdx.y * 64;
    int half = n0 >> 10;
    int jc0  = n0 & 1023;
    const float* wbase = W1 + (size_t)half * 1024 * 1024 + jc0;

    int arow = tid >> 2;
    int akq  = (tid & 3) * 4;
    int ar   = m0 + arow; if (ar > 799) ar = 799;
    const float* aptr = inst + (size_t)ar * 1024 + akq;
    int brow = tid >> 4;
    int bn   = (tid & 15) * 4;
    int tx = tid & 15, ty = tid >> 4;
    float acc[4][4] = {};

    for (int k0 = 0; k0 < 1024; k0 += 16) {
        float4 av = *(const float4*)(aptr + k0);
        float4 bv = *(const float4*)(wbase + (size_t)(k0 + brow) * 1024 + bn);
        As[akq+0][arow] = av.x; As[akq+1][arow] = av.y;
        As[akq+2][arow] = av.z; As[akq+3][arow] = av.w;
        *(float4*)&Bs[brow][bn] = bv;
        __syncthreads();
        #pragma unroll
        for (int kk = 0; kk < 16; kk++) {
            float af[4], bf[4];
            *(float4*)af = *(const float4*)&As[kk][ty*4];
            *(float4*)bf = *(const float4*)&Bs[kk][tx*4];
            #pragma unroll
            for (int i = 0; i < 4; i++)
                #pragma unroll
                for (int j = 0; j < 4; j++)
                    acc[i][j] += af[i] * bf[j];
        }
        __syncthreads();
    }
    #pragma unroll
    for (int i = 0; i < 4; i++) {
        int r = m0 + ty*4 + i;
        if (r < 800)
            *(float4*)&g_A12[(size_t)r*2048 + n0 + tx*4] =
                make_float4(acc[i][0], acc[i][1], acc[i][2], acc[i][3]);
    }
}

// =============================================================================
// K2 v7 (fused, fp16 3-product): h = lrelu(A@W1c + A12 gathers + b1);
// logits += h@W2 (FA2 pack, smem atomics). CTA 128x256, 512 thr (4Mx4N warps).
// =============================================================================
__device__ __forceinline__ void k2_load(uint32_t st, int tid, int k0,
                                        size_t rowbase, int p0, int n0)
{
    #pragma unroll 1
    for (int i = tid; i < 6144; i += 512) {
        int q = i & 7;
        const unsigned short* src;
        uint32_t dst;
        if (i < 2048) {
            int t = i >> 10;
            int r = (i >> 3) & 127;
            int p = p0 + r; if (p > NPAIR - 1) p = NPAIR - 1;
            src = (t ? g_Alo : g_Ahi) + (rowbase + p) * 1024 + k0 + q * 8;
            dst = st + t * K2A_LO + SWZ(r * 128 + q * 16);
        } else {
            int j = i - 2048;
            int t = j >> 11;               // 0: Bhi, 1: Blo
            int n = (j >> 3) & 255;
            src = (t ? g_Blo : g_Bhi) + (size_t)(n0 + n) * 1024 + k0 + q * 8;
            dst = st + (t ? K2B_LO : K2B_HI) + SWZ(n * 128 + q * 16);
        }
        cpasync16(dst, src);
    }
}

__global__ void __launch_bounds__(512, 1) k2_mma(const float* __restrict__ b1,
                                                 const int* __restrict__ connect,
                                                 float* __restrict__ out_logits)
{
    extern __shared__ __align__(1024) char smem[];
    uint32_t sb = smem_u32(smem);
    int tid = threadIdx.x;
    int lane = tid & 31, wid = tid >> 5;
    int wm = wid & 3, wn = wid >> 2;       // 4 M-warps x 4 N-warps
    int n0 = blockIdx.x * 256;
    int p0 = blockIdx.y * 128;
    int b  = blockIdx.z;
    size_t rowbase = (size_t)b * NPAIR;
    float* smemL = (float*)(smem + SMEML_OFF);

    for (int i = tid; i < 128*65; i += 512) smemL[i] = 0.f;

    float acc[2][8][4] = {};

    k2_load(sb,         tid, 0,  rowbase, p0, n0); CP_COMMIT();
    k2_load(sb + K2STG, tid, KC, rowbase, p0, n0); CP_COMMIT();

    #pragma unroll 1
    for (int c = 0; c < 16; c++) {
        if (c < 15) CP_WAIT(1);
        else        CP_WAIT(0);
        __syncthreads();

        uint32_t st  = sb + (c & 1) * K2STG;
        uint32_t sAh = st, sAl = st + K2A_LO, sBh = st + K2B_HI, sBl = st + K2B_LO;

        #pragma unroll
        for (int ks = 0; ks < 4; ks++) {
            int kb = ks * 32;
            uint32_t ah[2][4], al[2][4];
            #pragma unroll
            for (int mt = 0; mt < 2; mt++) {
                uint32_t off = SWZ((wm*32 + mt*16 + (lane & 15)) * 128 + kb + (lane >> 4) * 16);
                ldsm4(ah[mt], sAh + off);
                ldsm4(al[mt], sAl + off);
            }
            int nrow  = (lane & 7) + ((lane >> 4) & 1) * 8;
            int khalf = ((lane >> 3) & 1) * 16;
            {   // hi*hi + lo*hi
                uint32_t bh[4][4];
                #pragma unroll
                for (int ntq = 0; ntq < 4; ntq++) {
                    uint32_t off = SWZ((wn*64 + ntq*16 + nrow) * 128 + kb + khalf);
                    ldsm4(bh[ntq], sBh + off);
                }
                #pragma unroll
                for (int mt = 0; mt < 2; mt++)
                    #pragma unroll
                    for (int nt = 0; nt < 8; nt++) {
                        const uint32_t* bhp = &bh[nt >> 1][(nt & 1) * 2];
                        mma16816f(acc[mt][nt], ah[mt], bhp);
                        mma16816f(acc[mt][nt], al[mt], bhp);
                    }
            }
            {   // hi*lo
                uint32_t bl[4][4];
                #pragma unroll
                for (int ntq = 0; ntq < 4; ntq++) {
                    uint32_t off = SWZ((wn*64 + ntq*16 + nrow) * 128 + kb + khalf);
                    ldsm4(bl[ntq], sBl + off);
                }
                #pragma unroll
                for (int mt = 0; mt < 2; mt++)
                    #pragma unroll
                    for (int nt = 0; nt < 8; nt++) {
                        const uint32_t* blp = &bl[nt >> 1][(nt & 1) * 2];
                        mma16816f(acc[mt][nt], ah[mt], blp);
                    }
            }
        }
        __syncthreads();
        if (c + 2 < 16) {
            k2_load(sb + (c & 1) * K2STG, tid, (c + 2) * KC, rowbase, p0, n0);
            CP_COMMIT();
        }
    }

    // reuse stage-0 bytes for W2 tiles
    #pragma unroll 1
    for (int i = tid; i < 4096; i += 512) {
        int kind = i >> 11;
        int wnt  = (i >> 9) & 3;
        int n    = (i >> 3) & 63;
        int q    = i & 7;
        const unsigned short* src =
            (kind ? g_W2flo : g_W2fhi) + (size_t)n * 1024 + n0 + wnt * 64 + q * 8;
        uint32_t dst = sb + kind * 32768 + wnt * 8192 + SWZ(n * 128 + q * 16);
        cpasync16(dst, src);
    }
    CP_COMMIT();

    // ---- epilogue 1: gather-adds + lrelu (register-only) ----
    int gp = lane >> 2, tq = lane & 3;
    int n0w = n0 + wn * 64;
    size_t bb2 = (size_t)b * 2 * NPAIR;
    const float* a12b = g_A12 + (size_t)b * NINST * 2048;
    #pragma unroll
    for (int mt = 0; mt < 2; mt++) {
        #pragma unroll
        for (int half = 0; half < 2; half++) {
            int p = p0 + wm*32 + mt*16 + gp + half*8;
            if (p >= NPAIR) continue;
            int sub = connect[bb2 + p];
            int obj = connect[bb2 + NPAIR + p];
            const float* r1 = a12b + (size_t)sub * 2048 + n0w;
            const float* r2 = a12b + (size_t)obj * 2048 + 1024 + n0w;
            #pragma unroll
            for (int nt = 0; nt < 8; nt++) {
                int cc = nt*8 + tq*2;
                float2 v1 = *(const float2*)(r1 + cc);
                float2 v2 = *(const float2*)(r2 + cc);
                float2 vb = *(const float2*)(b1 + n0w + cc);
                float x = acc[mt][nt][half*2+0] + v1.x + v2.x + vb.x;
                float y = acc[mt][nt][half*2+1] + v1.y + v2.y + vb.y;
                acc[mt][nt][half*2+0] = x > 0.f ? x : 0.01f * x;
                acc[mt][nt][half*2+1] = y > 0.f ? y : 0.01f * y;
            }
        }
    }

    // ---- epilogue 2: pack h into fp16 hi/lo A-fragments (FA2 trick) ----
    uint32_t ahf[2][4][4], alf[2][4][4];
    #pragma unroll
    for (int mt = 0; mt < 2; mt++)
        #pragma unroll
        for (int j = 0; j < 4; j++)
            #pragma unroll
            for (int q = 0; q < 4; q++) {
                int nt = 2*j + (q >> 1);
                int ci = (q & 1) * 2;
                float x = acc[mt][nt][ci], y = acc[mt][nt][ci+1];
                uint32_t hp = packh2(x, y);
                __half2 hh = *(__half2*)&hp;
                ahf[mt][j][q] = hp;
                alf[mt][j][q] = packh2(x - __half2float(hh.x), y - __half2float(hh.y));
            }

    CP_WAIT(0);
    __syncthreads();

    // ---- epilogue 3: mini-GEMM h(32x64) @ W2(64k x 64n), 3 products ----
    uint32_t w2h = sb + wn * 8192;
    uint32_t w2l = sb + 32768 + wn * 8192;
    int nrow  = (lane & 7) + ((lane >> 4) & 1) * 8;
    int khalf = ((lane >> 3) & 1) * 16;
    #pragma unroll
    for (int nh = 0; nh < 2; nh++) {
        float acc2[2][4][4] = {};
        #pragma unroll
        for (int j = 0; j < 4; j++) {
            int kb = j * 32;
            uint32_t bh[2][4], bl[2][4];
            #pragma unroll
            for (int ntq = 0; ntq < 2; ntq++) {
                uint32_t off = SWZ((nh*32 + ntq*16 + nrow) * 128 + kb + khalf);
                ldsm4(bh[ntq], w2h + off);
                ldsm4(bl[ntq], w2l + off);
            }
            #pragma unroll
            for (int mt = 0; mt < 2; mt++)
                #pragma unroll
                for (int nt = 0; nt < 4; nt++) {
                    const uint32_t* bhp = &bh[nt >> 1][(nt & 1) * 2];
                    const uint32_t* blp = &bl[nt >> 1][(nt & 1) * 2];
                    mma16816f(acc2[mt][nt], ahf[mt][j], bhp);
                    mma16816f(acc2[mt][nt], alf[mt][j], bhp);
                    mma16816f(acc2[mt][nt], ahf[mt][j], blp);
                }
        }
        #pragma unroll
        for (int mt = 0; mt < 2; mt++)
            #pragma unroll
            for (int nt = 0; nt < 4; nt++)
                #pragma unroll
                for (int ci = 0; ci < 4; ci++) {
                    int row = wm*32 + mt*16 + gp + (ci >> 1) * 8;
                    int col = nh*32 + nt*8 + tq*2 + (ci & 1);
                    atomicAdd(&smemL[row*65 + col], acc2[mt][nt][ci]);
                }
    }
    __syncthreads();

    // ---- epilogue 4: REDG partial logits into global ----
    #pragma unroll 1
    for (int i = tid; i < 128*64; i += 512) {
        int row = i >> 6, col = i & 63;
        int p = p0 + row;
        if (p < NPAIR && col < NCLS)
            atomicAdd(&out_logits[((size_t)b*NPAIR + p)*NCLS + col], smemL[row*65 + col]);
    }
}

// =============================================================================
// K3b: softmax -> probs; dense decisions + margins
// =============================================================================
__global__ void k3b_softmax(const float* __restrict__ out_logits,
                            const float* __restrict__ scores,
                            const int*   __restrict__ connect,
                            float* __restrict__ out_probs)
{
    int row = blockIdx.x * blockDim.x + threadIdx.x;
    if (row >= NROWS) return;
    const float* lp = out_logits + (size_t)row * NCLS;
    float l[NCLS];
    float m = -1e30f;
    #pragma unroll
    for (int c = 0; c < NCLS; c++) { l[c] = lp[c]; m = fmaxf(m, l[c]); }
    float s = 0.f;
    #pragma unroll
    for (int c = 0; c < NCLS; c++) { l[c] = expf(l[c] - m); s += l[c]; }
    float inv = 1.0f / s;
    float* pp = out_probs + (size_t)row * NCLS;
    float best = 0.f, second = 0.f; int bidx = 0;
    #pragma unroll
    for (int c = 0; c < NCLS; c++) {
        float pr = l[c] * inv;
        pp[c] = pr;
        if (c >= 1) {
            if (pr > best) { second = best; best = pr; bidx = c; }
            else if (pr > second) second = pr;
        }
    }
    int b = row / NPAIR, p = row % NPAIR;
    int si = connect[(size_t)b*2*NPAIR + p];
    int oi = connect[(size_t)b*2*NPAIR + NPAIR + p];
    g_overall[row]  = best * scores[b*NINST + si] * scores[b*NINST + oi];
    g_predprob[row] = best;
    g_predlab[row]  = bidx;
    g_margin[row]   = best - second;
}

// =============================================================================
// K4: warp-tournament top-NCAND selection
// =============================================================================
__global__ __launch_bounds__(1024) void k4_select()
{
    __shared__ float vals[NPAIR];
    __shared__ float wmax[32];
    __shared__ int   warg[32];
    __shared__ int   s_win;
    int b = blockIdx.x, tid = threadIdx.x, w = tid >> 5, lane = tid & 31;
    for (int i = tid; i < NPAIR; i += 1024) vals[i] = g_overall[b*NPAIR + i];
    __syncthreads();

    int lo = w * 310;
    int hiv = lo + 310; if (hiv > NPAIR) hiv = NPAIR;
    float bv = -1.f; int bi = 0x7fffffff;
    for (int i = lo + lane; i < hiv; i += 32) {
        float v = vals[i];
        if (v > bv || (v == bv && i < bi)) { bv = v; bi = i; }
    }
    #pragma unroll
    for (int o = 16; o; o >>= 1) {
        float ov = __shfl_down_sync(0xffffffffu, bv, o);
        int   oi = __shfl_down_sync(0xffffffffu, bi, o);
        if (ov > bv || (ov == bv && oi < bi)) { bv = ov; bi = oi; }
    }
    if (lane == 0) { wmax[w] = bv; warg[w] = bi; }
    __syncthreads();

    for (int t = 0; t < NCAND; t++) {
        if (tid < 32) {
            float v = wmax[lane]; int i2 = warg[lane];
            #pragma unroll
            for (int o = 16; o; o >>= 1) {
                float ov = __shfl_down_sync(0xffffffffu, v, o);
                int   oi = __shfl_down_sync(0xffffffffu, i2, o);
                if (ov > v || (ov == v && oi < i2)) { v = ov; i2 = oi; }
            }
            if (lane == 0) {
                g_cand_idx[b*NCAND + t] = i2;
                vals[i2] = -2.f;
                s_win = i2 / 310;
            }
        }
        __syncthreads();
        if (w == s_win) {
            float nv = -1.f; int ni = 0x7fffffff;
            for (int i = lo + lane; i < hiv; i += 32) {
                float v = vals[i];
                if (v > nv || (v == nv && i < ni)) { nv = v; ni = i; }
            }
            #pragma unroll
            for (int o = 16; o; o >>= 1) {
                float ov = __shfl_down_sync(0xffffffffu, nv, o);
                int   oi = __shfl_down_sync(0xffffffffu, ni, o);
                if (ov > nv || (ov == nv && oi < ni)) { nv = ov; ni = oi; }
            }
            if (lane == 0) { wmax[w] = nv; warg[w] = ni; }
        }
        __syncthreads();
    }
}

// =============================================================================
// K4b: init candidate outputs with dense values; flag decision-critical ones
// =============================================================================
__global__ __launch_bounds__(NCAND) void k4b_flag()
{
    __shared__ float ov[NCAND];
    __shared__ int   fl[NCAND];
    int b = blockIdx.x, i = threadIdx.x;
    int cand = g_cand_idx[b*NCAND + i];
    int row  = b*NPAIR + cand;
    float o  = g_overall[row];
    ov[i] = o;
    __syncthreads();

    int f = (g_margin[row] < MARGIN) ? 1 : 0;
    for (int j = 0; j < NCAND; j++)
        if (j != i && fabsf(o - ov[j]) < MARGIN) f = 1;
    fl[i] = f;

    g_cand_ovr [b*NCAND + i] = (double)o;
    g_cand_prob[b*NCAND + i] = (double)g_predprob[row];
    g_cand_lab [b*NCAND + i] = g_predlab[row];
    __syncthreads();

    if (i == 0) {
        int n = 0;
        for (int j = 0; j < NCAND; j++)
            if (fl[j]) g_fix_list[b*NCAND + (n++)] = j;
        g_fix_cnt[b] = n;
    }
}

// =============================================================================
// K5: compensated-fp32 exact partial h — FLAGGED candidates only
// =============================================================================
#define CPB 4
__global__ __launch_bounds__(256) void k5_repair_h(const float* __restrict__ inst,
                                                   const float* __restrict__ phrase,
                                                   const float* __restrict__ W1,
                                                   const int*   __restrict__ connect,
                                                   const int*   __restrict__ pidx)
{
    __shared__ float sf[CPB][1536];
    int ks = blockIdx.x;
    int g  = blockIdx.y;
    int b  = blockIdx.z;
    int tid = threadIdx.x;
    int k0 = ks * 1536;

    int cnt = g_fix_cnt[b];
    if (g * CPB >= cnt) return;
    int slots[CPB];

    #pragma unroll 1
    for (int c = 0; c < CPB; c++) {
        int jj = g*CPB + c; if (jj > cnt - 1) jj = cnt - 1;
        int slot = b*NCAND + g_fix_list[b*NCAND + jj];
        slots[c] = slot;
        int p  = g_cand_idx[slot];
        int si = connect[(size_t)b*2*NPAIR + p];
        int oi = connect[(size_t)b*2*NPAIR + NPAIR + p];
        int ph = pidx[b*NPAIR + p];
        const float* s0 = inst   + ((size_t)b*NINST + si)*1024;
        const float* s1 = inst   + ((size_t)b*NINST + oi)*1024;
        const float* s2 = phrase + ((size_t)b*NPAIR + ph)*1024;
        for (int k = tid; k < 1536; k += 256) {
            int f = k0 + k;
            float v;
            if (f < 1024)       v = s0[f];
            else if (f < 2048)  v = s1[f - 1024];
            else                v = s2[f - 2048];
            sf[c][k] = v;
        }
    }
    __syncthreads();

    float s[CPB][4] = {};
    float comp[CPB][4] = {};
    const float* wcol = W1 + (size_t)k0 * 1024 + tid * 4;
    #pragma unroll 2
    for (int k = 0; k < 1536; k++) {
        float4 w = *(const float4*)(wcol + (size_t)k * 1024);
        float wv[4] = {w.x, w.y, w.z, w.w};
        #pragma unroll
        for (int c = 0; c < CPB; c++) {
            float f = sf[c][k];
            #pragma unroll
            for (int j = 0; j < 4; j++) {
                float p  = __fmul_rn(f, wv[j]);
                float e  = __fmaf_rn(f, wv[j], -p);
                float t  = __fadd_rn(s[c][j], p);
                float z  = __fsub_rn(t, s[c][j]);
                float e2 = __fadd_rn(__fsub_rn(s[c][j], __fsub_rn(t, z)),
                                     __fsub_rn(p, z));
                comp[c][j] = __fadd_rn(comp[c][j], __fadd_rn(e2, e));
                s[c][j] = t;
            }
        }
    }
    float* outs = g_hs[ks];
    float* outc = g_hc[ks];
    #pragma unroll
    for (int c = 0; c < CPB; c++) {
        int slot = slots[c];
        *(float4*)(outs + (size_t)slot*1024 + tid*4) =
            make_float4(s[c][0], s[c][1], s[c][2], s[c][3]);
        *(float4*)(outc + (size_t)slot*1024 + tid*4) =
            make_float4(comp[c][0], comp[c][1], comp[c][2], comp[c][3]);
    }
}

// =============================================================================
// K6: exact decisions — FLAGGED candidates only
// =============================================================================
__global__ __launch_bounds__(64) void k6_decide(const float* __restrict__ W2,
                                                const float* __restrict__ b2,
                                                const float* __restrict__ b1,
                                                const float* __restrict__ scores,
                                                const int*   __restrict__ connect)
{
    __shared__ double sh[1024];
    __shared__ double slog[NCLS];
    int gid = blockIdx.x;
    int b = gid >> 7, j = gid & (NCAND - 1);
    if (j >= g_fix_cnt[b]) return;
    int slot = b*NCAND + g_fix_list[b*NCAND + j];
    int tid = threadIdx.x;
    size_t base = (size_t)slot * 1024;
    for (int k = tid; k < 1024; k += 64) {
        double v = ((double)g_hs[0][base + k] + (double)g_hc[0][base + k])
                 + ((double)g_hs[1][base + k] + (double)g_hc[1][base + k])
                 + (double)b1[k];
        v = v > 0.0 ? v : 0.01 * v;
        sh[k] = v;
    }
    __syncthreads();

    if (tid < NCLS) {
        double acc = 0.0;
        #pragma unroll 8
        for (int k = 0; k < 1024; k++)
            acc = fma(sh[k], (double)W2[(size_t)k*NCLS + tid], acc);
        slog[tid] = acc + (double)b2[tid];
    }
    __syncthreads();

    if (tid == 0) {
        double m = slog[0];
        for (int c = 1; c < NCLS; c++) m = slog[c] > m ? slog[c] : m;
        double e[NCLS]; double ssum = 0.0;
        for (int c = 0; c < NCLS; c++) { e[c] = exp(slog[c] - m); ssum += e[c]; }
        double best = 0.0; int bl = 0;
        for (int c = 1; c < NCLS; c++) {
            double pr = e[c] / ssum;
            if (pr > best) { best = pr; bl = c; }
        }
        int p = g_cand_idx[slot];
        int si = connect[(size_t)b*2*NPAIR + p];
        int oi = connect[(size_t)b*2*NPAIR + NPAIR + p];
        double ov = best * (double)scores[b*NINST + si] * (double)scores[b*NINST + oi];
        g_cand_ovr[slot]  = ov;
        g_cand_prob[slot] = best;
        g_cand_lab[slot]  = bl;
    }
}

// =============================================================================
// K7: final top-100 per batch over NCAND candidates
// =============================================================================
__global__ __launch_bounds__(128) void k7_final(float* __restrict__ outbase)
{
    __shared__ double v[NCAND];
    __shared__ int    pix[NCAND];
    int b = blockIdx.x, tid = threadIdx.x;
    v[tid]   = g_cand_ovr[b*NCAND + tid];
    pix[tid] = g_cand_idx[b*NCAND + tid];
    __syncthreads();

    if (tid == 0) {
        float* out_lab  = outbase;
        float* out_prob = outbase + 800;
        float* out_val  = outbase + 1600;
        float* out_idx  = outbase + 2400;
        for (int t = 0; t < 100; t++) {
            double bv = -1.0; int bj = 0; int bidx = 0x7fffffff;
            for (int j = 0; j < NCAND; j++) {
                double val = v[j]; int ix = pix[j];
                if (val > bv || (val == bv && ix < bidx)) { bv = val; bj = j; bidx = ix; }
            }
            int slot2 = b*NCAND + bj;
            out_val [b*100 + t] = (float)bv;
            out_idx [b*100 + t] = (float)bidx;
            out_lab [b*100 + t] = (float)g_cand_lab[slot2];
            out_prob[b*100 + t] = (float)g_cand_prob[slot2];
            v[bj] = -2.0;
        }
    }
}

// =============================================================================
extern "C" void kernel_launch(void* const* d_in, const int* in_sizes, int n_in,
                              void* d_out, int out_size)
{
    const float* inst    = (const float*)d_in[0];
    const float* phrase  = (const float*)d_in[1];
    const float* scores  = (const float*)d_in[2];
    const float* W1      = (const float*)d_in[3];
    const float* b1      = (const float*)d_in[4];
    const float* W2      = (const float*)d_in[5];
    const float* b2      = (const float*)d_in[6];
    const int*   connect = (const int*)d_in[7];
    const int*   pidx    = (const int*)d_in[8];

    float* out        = (float*)d_out;
    float* out_logits = out;
    float* out_probs  = out + (size_t)BATCH*NPAIR*NCLS;
    float* out_top    = out + (size_t)2*BATCH*NPAIR*NCLS;

    cudaFuncSetAttribute(k2_mma, cudaFuncAttributeMaxDynamicSharedMemorySize, K2_SMEM);

    kprep_all<<<1088, 256>>>(W1, W2, b2, out_logits);
    kprep_a<<<NROWS, 256>>>(phrase, pidx);
    k1_instproj<<<dim3(32, 13), 256>>>(inst, W1);
    k2_mma<<<dim3(4, 78, BATCH), 512, K2_SMEM>>>(b1, connect, out_logits);
    k3b_softmax<<<(NROWS + 255) / 256, 256>>>(out_logits, scores, connect, out_probs);
    k4_select<<<BATCH, 1024>>>();
    k4b_flag<<<BATCH, NCAND>>>();
    k5_repair_h<<<dim3(2, 32, BATCH), 256>>>(inst, phrase, W1, connect, pidx);
    k6_decide<<<BATCH*NCAND, 64>>>(W2, b2, b1, scores, connect);
    k7_final<<<BATCH, 128>>>(out_top);
}

// round 15
// speedup vs baseline: 1.0501x; 1.0019x over previous
#include <cuda_runtime.h>
#include <cuda_bf16.h>
#include <cuda_fp16.h>
#include <math.h>
#include <stdint.h>

#define BATCH 8
#define NINST 100
#define NPAIR 9900
#define NCLS  51
#define NROWS (BATCH*NPAIR)   // 79200
#define NCAND 128
#define KC    32
#define MARGIN 2e-5f
// k2: CTA 128x128, 2 stages of 32KB (Ahi 8K | Alo 8K | Bhi 8K | Blo 8K), SW64.
// W2 (32KB) reuses stage-0 bytes after the mainloop. smemL after stages.
#define K2A_LO 8192
#define K2B_HI 16384
#define K2B_LO 24576
#define K2STG  32768
#define SMEML_OFF (2*K2STG)                // 65536
#define K2_SMEM   (SMEML_OFF + 128*65*4)   // 98816  -> 2 CTAs/SM

// ---------------- scratch (device globals; no allocs allowed) ----------------
__device__ float  g_A12[BATCH*NINST*2048];
__device__ float  g_overall[NROWS];
__device__ float  g_predprob[NROWS];
__device__ float  g_margin[NROWS];
__device__ int    g_predlab[NROWS];
__device__ int    g_cand_idx[BATCH*NCAND];
__device__ int    g_cand_lab[BATCH*NCAND];
__device__ double g_cand_prob[BATCH*NCAND];
__device__ double g_cand_ovr[BATCH*NCAND];
__device__ int    g_fix_list[BATCH*NCAND];
__device__ int    g_fix_cnt[BATCH];
__device__ float  g_hs[2][BATCH*NCAND*1024];
__device__ float  g_hc[2][BATCH*NCAND*1024];
__device__ __align__(16) unsigned short g_Ahi[81100800];   // gathered phrase fp16 hi
__device__ __align__(16) unsigned short g_Alo[81100800];   // fp16 lo
__device__ __align__(16) unsigned short g_Bhi[1024*1024];  // W1c^T [n][k] fp16 hi
__device__ __align__(16) unsigned short g_Blo[1024*1024];  // fp16 lo
__device__ __align__(16) unsigned short g_W2fhi[64*1024];  // W2^T padded fp16 hi
__device__ __align__(16) unsigned short g_W2flo[64*1024];  // fp16 lo

// ---------------- helpers (baseline PTX only) ----------------
__device__ __forceinline__ uint32_t smem_u32(const void* p) {
    uint32_t a;
    asm("{ .reg .u64 t; cvta.to.shared.u64 t, %1; cvt.u32.u64 %0, t; }" : "=r"(a) : "l"(p));
    return a;
}
#define SWZ(x)   ((x) ^ (((x) >> 3) & 0x70))   // 128B-row swizzle
#define SWZ64(x) ((x) ^ (((x) >> 3) & 0x30))   // 64B-row swizzle
__device__ __forceinline__ void cpasync16(uint32_t dst, const void* src) {
    asm volatile("cp.async.cg.shared.global [%0], [%1], 16;" :: "r"(dst), "l"(src));
}
#define CP_COMMIT() asm volatile("cp.async.commit_group;" ::: "memory")
#define CP_WAIT(n)  asm volatile("cp.async.wait_group %0;" :: "n"(n) : "memory")
__device__ __forceinline__ void ldsm4(uint32_t* r, uint32_t addr) {
    asm volatile("ldmatrix.sync.aligned.m8n8.x4.shared.b16 {%0,%1,%2,%3}, [%4];"
        : "=r"(r[0]), "=r"(r[1]), "=r"(r[2]), "=r"(r[3]) : "r"(addr));
}
__device__ __forceinline__ void mma16816f(float* c, const uint32_t* a, const uint32_t* b) {
    asm volatile("mma.sync.aligned.m16n8k16.row.col.f32.f16.f16.f32 "
        "{%0,%1,%2,%3}, {%4,%5,%6,%7}, {%8,%9}, {%0,%1,%2,%3};"
        : "+f"(c[0]), "+f"(c[1]), "+f"(c[2]), "+f"(c[3])
        : "r"(a[0]), "r"(a[1]), "r"(a[2]), "r"(a[3]), "r"(b[0]), "r"(b[1]));
}
__device__ __forceinline__ uint32_t packh2(float x, float y) {
    __half2 t;
    t.x = __float2half_rn(x);
    t.y = __float2half_rn(y);
    return *(uint32_t*)&t;
}

// =============================================================================
// kprep_all: [0..1023] W1c -> g_Bhi/g_Blo; [1024..1087] W2 -> g_W2f* + init
// =============================================================================
__global__ __launch_bounds__(256) void kprep_all(const float* __restrict__ W1,
                                                 const float* __restrict__ W2,
                                                 const float* __restrict__ b2,
                                                 float* __restrict__ out_logits)
{
    int bid = blockIdx.x;
    if (bid < 1024) {
        __shared__ float t[32][33];
        int kk0 = (bid & 31) * 32, nn0 = (bid >> 5) * 32;
        int tx = threadIdx.x & 31, ty = threadIdx.x >> 5;
        #pragma unroll
        for (int i = 0; i < 32; i += 8)
            t[ty + i][tx] = W1[(size_t)(2048 + kk0 + ty + i) * 1024 + nn0 + tx];
        __syncthreads();
        #pragma unroll
        for (int i = 0; i < 32; i += 8) {
            float x = t[tx][ty + i];
            __half h = __float2half_rn(x);
            float lo = x - __half2float(h);
            size_t o = (size_t)(nn0 + ty + i) * 1024 + kk0 + tx;
            g_Bhi[o] = __half_as_ushort(h);
            g_Blo[o] = __half_as_ushort(__float2half_rn(lo));
        }
    } else {
        int n = bid - 1024;
        for (int k = threadIdx.x; k < 1024; k += 256) {
            float x = (n < NCLS) ? W2[(size_t)k * NCLS + n] : 0.f;
            __half h = __float2half_rn(x);
            float lo = x - __half2float(h);
            g_W2fhi[n * 1024 + k] = __half_as_ushort(h);
            g_W2flo[n * 1024 + k] = __half_as_ushort(__float2half_rn(lo));
        }
        for (int i = n * 256 + threadIdx.x; i < NROWS * NCLS; i += 64 * 256)
            out_logits[i] = b2[i % NCLS];
    }
}

// =============================================================================
// prep_a: gather phrase rows per pair, split into fp16 hi/lo
// =============================================================================
__global__ __launch_bounds__(256) void kprep_a(const float* __restrict__ phrase,
                                               const int* __restrict__ pidx)
{
    int r = blockIdx.x;
    int b = r / NPAIR;
    int ph = pidx[r];
    const float4* src = (const float4*)(phrase + ((size_t)b * NPAIR + ph) * 1024);
    float4 v = src[threadIdx.x];
    ushort4 hi, lo;
    #define SPL(c, hf, lf) { __half _h = __float2half_rn(v.c); \
        float _l = v.c - __half2float(_h); \
        hf = __half_as_ushort(_h); lf = __half_as_ushort(__float2half_rn(_l)); }
    SPL(x, hi.x, lo.x) SPL(y, hi.y, lo.y) SPL(z, hi.z, lo.z) SPL(w, hi.w, lo.w)
    #undef SPL
    size_t o = (size_t)r * 1024 + threadIdx.x * 4;
    *(ushort4*)(g_Ahi + o) = hi;
    *(ushort4*)(g_Alo + o) = lo;
}

// =============================================================================
// K1: A12[r, j] = inst[r, :] @ W1[half*1024 + :, jc]   (fp32, small)
// =============================================================================
__global__ __launch_bounds__(256) void k1_instproj(const float* __restrict__ inst,
                                                   const float* __restrict__ W1)
{
    __shared__ float As[16][68];
    __shared__ float Bs[16][64];
    int tid = threadIdx.x;
    int n0 = blockIdx.x * 64;
    int m0 = blockIdx.y * 64;
    int half = n0 >> 10;
    int jc0  = n0 & 1023;
    const float* wbase = W1 + (size_t)half * 1024 * 1024 + jc0;

    int arow = tid >> 2;
    int akq  = (tid & 3) * 4;
    int ar   = m0 + arow; if (ar > 799) ar = 799;
    const float* aptr = inst + (size_t)ar * 1024 + akq;
    int brow = tid >> 4;
    int bn   = (tid & 15) * 4;
    int tx = tid & 15, ty = tid >> 4;
    float acc[4][4] = {};

    for (int k0 = 0; k0 < 1024; k0 += 16) {
        float4 av = *(const float4*)(aptr + k0);
        float4 bv = *(const float4*)(wbase + (size_t)(k0 + brow) * 1024 + bn);
        As[akq+0][arow] = av.x; As[akq+1][arow] = av.y;
        As[akq+2][arow] = av.z; As[akq+3][arow] = av.w;
        *(float4*)&Bs[brow][bn] = bv;
        __syncthreads();
        #pragma unroll
        for (int kk = 0; kk < 16; kk++) {
            float af[4], bf[4];
            *(float4*)af = *(const float4*)&As[kk][ty*4];
            *(float4*)bf = *(const float4*)&Bs[kk][tx*4];
            #pragma unroll
            for (int i = 0; i < 4; i++)
                #pragma unroll
                for (int j = 0; j < 4; j++)
                    acc[i][j] += af[i] * bf[j];
        }
        __syncthreads();
    }
    #pragma unroll
    for (int i = 0; i < 4; i++) {
        int r = m0 + ty*4 + i;
        if (r < 800)
            *(float4*)&g_A12[(size_t)r*2048 + n0 + tx*4] =
                make_float4(acc[i][0], acc[i][1], acc[i][2], acc[i][3]);
    }
}

// =============================================================================
// K2 v8 (fused, fp16 3-product, 2 CTA/SM): CTA 128x128, 256 thr (4M x 2N),
// warp tile 32x64, KC=32 (SW64, 64B rows), 2 stages of 32KB.
// h = lrelu(A@W1c + A12 gathers + b1); logits += h@W2 (FA2 pack, smem atomics).
// =============================================================================
__device__ __forceinline__ void k2_load(uint32_t st, int tid, int k0,
                                        size_t rowbase, int p0, int n0)
{
    #pragma unroll 1
    for (int i = tid; i < 2048; i += 256) {
        int q = i & 3;
        const unsigned short* src;
        uint32_t dst;
        if (i < 1024) {
            int t = i >> 9;
            int r = (i >> 2) & 127;
            int p = p0 + r; if (p > NPAIR - 1) p = NPAIR - 1;
            src = (t ? g_Alo : g_Ahi) + (rowbase + p) * 1024 + k0 + q * 8;
            dst = st + t * K2A_LO + SWZ64(r * 64 + q * 16);
        } else {
            int j = i - 1024;
            int t = j >> 9;
            int n = (j >> 2) & 127;
            src = (t ? g_Blo : g_Bhi) + (size_t)(n0 + n) * 1024 + k0 + q * 8;
            dst = st + (t ? K2B_LO : K2B_HI) + SWZ64(n * 64 + q * 16);
        }
        cpasync16(dst, src);
    }
}

__global__ void __launch_bounds__(256, 2) k2_mma(const float* __restrict__ b1,
                                                 const int* __restrict__ connect,
                                                 float* __restrict__ out_logits)
{
    extern __shared__ __align__(1024) char smem[];
    uint32_t sb = smem_u32(smem);
    int tid = threadIdx.x;
    int lane = tid & 31, wid = tid >> 5;
    int wm = wid & 3, wn = wid >> 2;       // 4 M-warps x 2 N-warps
    int n0 = blockIdx.x * 128;
    int p0 = blockIdx.y * 128;
    int b  = blockIdx.z;
    size_t rowbase = (size_t)b * NPAIR;
    float* smemL = (float*)(smem + SMEML_OFF);

    for (int i = tid; i < 128*65; i += 256) smemL[i] = 0.f;

    float acc[2][8][4] = {};

    k2_load(sb,         tid, 0,  rowbase, p0, n0); CP_COMMIT();
    k2_load(sb + K2STG, tid, KC, rowbase, p0, n0); CP_COMMIT();

    #pragma unroll 1
    for (int c = 0; c < 32; c++) {
        if (c < 31) CP_WAIT(1);
        else        CP_WAIT(0);
        __syncthreads();

        uint32_t st  = sb + (c & 1) * K2STG;
        uint32_t sAh = st, sAl = st + K2A_LO, sBh = st + K2B_HI, sBl = st + K2B_LO;

        #pragma unroll
        for (int ks = 0; ks < 2; ks++) {
            int kb = ks * 32;
            uint32_t ah[2][4], al[2][4];
            #pragma unroll
            for (int mt = 0; mt < 2; mt++) {
                uint32_t off = SWZ64((wm*32 + mt*16 + (lane & 15)) * 64 + kb + (lane >> 4) * 16);
                ldsm4(ah[mt], sAh + off);
                ldsm4(al[mt], sAl + off);
            }
            int nrow  = (lane & 7) + ((lane >> 4) & 1) * 8;
            int khalf = ((lane >> 3) & 1) * 16;
            {   // hi*hi + lo*hi
                uint32_t bh[4][4];
                #pragma unroll
                for (int ntq = 0; ntq < 4; ntq++) {
                    uint32_t off = SWZ64((wn*64 + ntq*16 + nrow) * 64 + kb + khalf);
                    ldsm4(bh[ntq], sBh + off);
                }
                #pragma unroll
                for (int mt = 0; mt < 2; mt++)
                    #pragma unroll
                    for (int nt = 0; nt < 8; nt++) {
                        const uint32_t* bhp = &bh[nt >> 1][(nt & 1) * 2];
                        mma16816f(acc[mt][nt], ah[mt], bhp);
                        mma16816f(acc[mt][nt], al[mt], bhp);
                    }
            }
            {   // hi*lo
                uint32_t bl[4][4];
                #pragma unroll
                for (int ntq = 0; ntq < 4; ntq++) {
                    uint32_t off = SWZ64((wn*64 + ntq*16 + nrow) * 64 + kb + khalf);
                    ldsm4(bl[ntq], sBl + off);
                }
                #pragma unroll
                for (int mt = 0; mt < 2; mt++)
                    #pragma unroll
                    for (int nt = 0; nt < 8; nt++) {
                        const uint32_t* blp = &bl[nt >> 1][(nt & 1) * 2];
                        mma16816f(acc[mt][nt], ah[mt], blp);
                    }
            }
        }
        __syncthreads();
        if (c + 2 < 32) {
            k2_load(sb + (c & 1) * K2STG, tid, (c + 2) * KC, rowbase, p0, n0);
            CP_COMMIT();
        }
    }

    // reuse stage-0 bytes for W2 tiles: [2 kinds][2 wnt][64n x 64k] SW128
    #pragma unroll 1
    for (int i = tid; i < 2048; i += 256) {
        int kind = i >> 10;
        int wnt  = (i >> 9) & 1;
        int n    = (i >> 3) & 63;
        int q    = i & 7;
        const unsigned short* src =
            (kind ? g_W2flo : g_W2fhi) + (size_t)n * 1024 + n0 + wnt * 64 + q * 8;
        uint32_t dst = sb + kind * 16384 + wnt * 8192 + SWZ(n * 128 + q * 16);
        cpasync16(dst, src);
    }
    CP_COMMIT();

    // ---- epilogue 1: gather-adds + lrelu (register-only) ----
    int gp = lane >> 2, tq = lane & 3;
    int n0w = n0 + wn * 64;
    size_t bb2 = (size_t)b * 2 * NPAIR;
    const float* a12b = g_A12 + (size_t)b * NINST * 2048;
    #pragma unroll
    for (int mt = 0; mt < 2; mt++) {
        #pragma unroll
        for (int half = 0; half < 2; half++) {
            int p = p0 + wm*32 + mt*16 + gp + half*8;
            if (p >= NPAIR) continue;
            int sub = connect[bb2 + p];
            int obj = connect[bb2 + NPAIR + p];
            const float* r1 = a12b + (size_t)sub * 2048 + n0w;
            const float* r2 = a12b + (size_t)obj * 2048 + 1024 + n0w;
            #pragma unroll
            for (int nt = 0; nt < 8; nt++) {
                int cc = nt*8 + tq*2;
                float2 v1 = *(const float2*)(r1 + cc);
                float2 v2 = *(const float2*)(r2 + cc);
                float2 vb = *(const float2*)(b1 + n0w + cc);
                float x = acc[mt][nt][half*2+0] + v1.x + v2.x + vb.x;
                float y = acc[mt][nt][half*2+1] + v1.y + v2.y + vb.y;
                acc[mt][nt][half*2+0] = x > 0.f ? x : 0.01f * x;
                acc[mt][nt][half*2+1] = y > 0.f ? y : 0.01f * y;
            }
        }
    }

    // ---- epilogue 2: pack h into fp16 hi/lo A-fragments (FA2 trick) ----
    uint32_t ahf[2][4][4], alf[2][4][4];
    #pragma unroll
    for (int mt = 0; mt < 2; mt++)
        #pragma unroll
        for (int j = 0; j < 4; j++)
            #pragma unroll
            for (int q = 0; q < 4; q++) {
                int nt = 2*j + (q >> 1);
                int ci = (q & 1) * 2;
                float x = acc[mt][nt][ci], y = acc[mt][nt][ci+1];
                uint32_t hp = packh2(x, y);
                __half2 hh = *(__half2*)&hp;
                ahf[mt][j][q] = hp;
                alf[mt][j][q] = packh2(x - __half2float(hh.x), y - __half2float(hh.y));
            }

    CP_WAIT(0);
    __syncthreads();

    // ---- epilogue 3: mini-GEMM h(32x64) @ W2(64k x 64n), 3 products ----
    uint32_t w2h = sb + wn * 8192;
    uint32_t w2l = sb + 16384 + wn * 8192;
    int nrow  = (lane & 7) + ((lane >> 4) & 1) * 8;
    int khalf = ((lane >> 3) & 1) * 16;
    #pragma unroll
    for (int nh = 0; nh < 2; nh++) {
        float acc2[2][4][4] = {};
        #pragma unroll
        for (int j = 0; j < 4; j++) {
            int kb = j * 32;
            uint32_t bh[2][4], bl[2][4];
            #pragma unroll
            for (int ntq = 0; ntq < 2; ntq++) {
                uint32_t off = SWZ((nh*32 + ntq*16 + nrow) * 128 + kb + khalf);
                ldsm4(bh[ntq], w2h + off);
                ldsm4(bl[ntq], w2l + off);
            }
            #pragma unroll
            for (int mt = 0; mt < 2; mt++)
                #pragma unroll
                for (int nt = 0; nt < 4; nt++) {
                    const uint32_t* bhp = &bh[nt >> 1][(nt & 1) * 2];
                    const uint32_t* blp = &bl[nt >> 1][(nt & 1) * 2];
                    mma16816f(acc2[mt][nt], ahf[mt][j], bhp);
                    mma16816f(acc2[mt][nt], alf[mt][j], bhp);
                    mma16816f(acc2[mt][nt], ahf[mt][j], blp);
                }
        }
        #pragma unroll
        for (int mt = 0; mt < 2; mt++)
            #pragma unroll
            for (int nt = 0; nt < 4; nt++)
                #pragma unroll
                for (int ci = 0; ci < 4; ci++) {
                    int row = wm*32 + mt*16 + gp + (ci >> 1) * 8;
                    int col = nh*32 + nt*8 + tq*2 + (ci & 1);
                    atomicAdd(&smemL[row*65 + col], acc2[mt][nt][ci]);
                }
    }
    __syncthreads();

    // ---- epilogue 4: REDG partial logits into global ----
    #pragma unroll 1
    for (int i = tid; i < 128*64; i += 256) {
        int row = i >> 6, col = i & 63;
        int p = p0 + row;
        if (p < NPAIR && col < NCLS)
            atomicAdd(&out_logits[((size_t)b*NPAIR + p)*NCLS + col], smemL[row*65 + col]);
    }
}

// =============================================================================
// K3b: softmax -> probs; dense decisions + margins
// =============================================================================
__global__ void k3b_softmax(const float* __restrict__ out_logits,
                            const float* __restrict__ scores,
                            const int*   __restrict__ connect,
                            float* __restrict__ out_probs)
{
    int row = blockIdx.x * blockDim.x + threadIdx.x;
    if (row >= NROWS) return;
    const float* lp = out_logits + (size_t)row * NCLS;
    float l[NCLS];
    float m = -1e30f;
    #pragma unroll
    for (int c = 0; c < NCLS; c++) { l[c] = lp[c]; m = fmaxf(m, l[c]); }
    float s = 0.f;
    #pragma unroll
    for (int c = 0; c < NCLS; c++) { l[c] = expf(l[c] - m); s += l[c]; }
    float inv = 1.0f / s;
    float* pp = out_probs + (size_t)row * NCLS;
    float best = 0.f, second = 0.f; int bidx = 0;
    #pragma unroll
    for (int c = 0; c < NCLS; c++) {
        float pr = l[c] * inv;
        pp[c] = pr;
        if (c >= 1) {
            if (pr > best) { second = best; best = pr; bidx = c; }
            else if (pr > second) second = pr;
        }
    }
    int b = row / NPAIR, p = row % NPAIR;
    int si = connect[(size_t)b*2*NPAIR + p];
    int oi = connect[(size_t)b*2*NPAIR + NPAIR + p];
    g_overall[row]  = best * scores[b*NINST + si] * scores[b*NINST + oi];
    g_predprob[row] = best;
    g_predlab[row]  = bidx;
    g_margin[row]   = best - second;
}

// =============================================================================
// K4: warp-tournament top-NCAND selection
// =============================================================================
__global__ __launch_bounds__(1024) void k4_select()
{
    __shared__ float vals[NPAIR];
    __shared__ float wmax[32];
    __shared__ int   warg[32];
    __shared__ int   s_win;
    int b = blockIdx.x, tid = threadIdx.x, w = tid >> 5, lane = tid & 31;
    for (int i = tid; i < NPAIR; i += 1024) vals[i] = g_overall[b*NPAIR + i];
    __syncthreads();

    int lo = w * 310;
    int hiv = lo + 310; if (hiv > NPAIR) hiv = NPAIR;
    float bv = -1.f; int bi = 0x7fffffff;
    for (int i = lo + lane; i < hiv; i += 32) {
        float v = vals[i];
        if (v > bv || (v == bv && i < bi)) { bv = v; bi = i; }
    }
    #pragma unroll
    for (int o = 16; o; o >>= 1) {
        float ov = __shfl_down_sync(0xffffffffu, bv, o);
        int   oi = __shfl_down_sync(0xffffffffu, bi, o);
        if (ov > bv || (ov == bv && oi < bi)) { bv = ov; bi = oi; }
    }
    if (lane == 0) { wmax[w] = bv; warg[w] = bi; }
    __syncthreads();

    for (int t = 0; t < NCAND; t++) {
        if (tid < 32) {
            float v = wmax[lane]; int i2 = warg[lane];
            #pragma unroll
            for (int o = 16; o; o >>= 1) {
                float ov = __shfl_down_sync(0xffffffffu, v, o);
                int   oi = __shfl_down_sync(0xffffffffu, i2, o);
                if (ov > v || (ov == v && oi < i2)) { v = ov; i2 = oi; }
            }
            if (lane == 0) {
                g_cand_idx[b*NCAND + t] = i2;
                vals[i2] = -2.f;
                s_win = i2 / 310;
            }
        }
        __syncthreads();
        if (w == s_win) {
            float nv = -1.f; int ni = 0x7fffffff;
            for (int i = lo + lane; i < hiv; i += 32) {
                float v = vals[i];
                if (v > nv || (v == nv && i < ni)) { nv = v; ni = i; }
            }
            #pragma unroll
            for (int o = 16; o; o >>= 1) {
                float ov = __shfl_down_sync(0xffffffffu, nv, o);
                int   oi = __shfl_down_sync(0xffffffffu, ni, o);
                if (ov > nv || (ov == nv && oi < ni)) { nv = ov; ni = oi; }
            }
            if (lane == 0) { wmax[w] = nv; warg[w] = ni; }
        }
        __syncthreads();
    }
}

// =============================================================================
// K4b: init candidate outputs with dense values; flag decision-critical ones
// =============================================================================
__global__ __launch_bounds__(NCAND) void k4b_flag()
{
    __shared__ float ov[NCAND];
    __shared__ int   fl[NCAND];
    int b = blockIdx.x, i = threadIdx.x;
    int cand = g_cand_idx[b*NCAND + i];
    int row  = b*NPAIR + cand;
    float o  = g_overall[row];
    ov[i] = o;
    __syncthreads();

    int f = (g_margin[row] < MARGIN) ? 1 : 0;
    for (int j = 0; j < NCAND; j++)
        if (j != i && fabsf(o - ov[j]) < MARGIN) f = 1;
    fl[i] = f;

    g_cand_ovr [b*NCAND + i] = (double)o;
    g_cand_prob[b*NCAND + i] = (double)g_predprob[row];
    g_cand_lab [b*NCAND + i] = g_predlab[row];
    __syncthreads();

    if (i == 0) {
        int n = 0;
        for (int j = 0; j < NCAND; j++)
            if (fl[j]) g_fix_list[b*NCAND + (n++)] = j;
        g_fix_cnt[b] = n;
    }
}

// =============================================================================
// K5: compensated-fp32 exact partial h — FLAGGED candidates only
// =============================================================================
#define CPB 4
__global__ __launch_bounds__(256) void k5_repair_h(const float* __restrict__ inst,
                                                   const float* __restrict__ phrase,
                                                   const float* __restrict__ W1,
                                                   const int*   __restrict__ connect,
                                                   const int*   __restrict__ pidx)
{
    __shared__ float sf[CPB][1536];
    int ks = blockIdx.x;
    int g  = blockIdx.y;
    int b  = blockIdx.z;
    int tid = threadIdx.x;
    int k0 = ks * 1536;

    int cnt = g_fix_cnt[b];
    if (g * CPB >= cnt) return;
    int slots[CPB];

    #pragma unroll 1
    for (int c = 0; c < CPB; c++) {
        int jj = g*CPB + c; if (jj > cnt - 1) jj = cnt - 1;
        int slot = b*NCAND + g_fix_list[b*NCAND + jj];
        slots[c] = slot;
        int p  = g_cand_idx[slot];
        int si = connect[(size_t)b*2*NPAIR + p];
        int oi = connect[(size_t)b*2*NPAIR + NPAIR + p];
        int ph = pidx[b*NPAIR + p];
        const float* s0 = inst   + ((size_t)b*NINST + si)*1024;
        const float* s1 = inst   + ((size_t)b*NINST + oi)*1024;
        const float* s2 = phrase + ((size_t)b*NPAIR + ph)*1024;
        for (int k = tid; k < 1536; k += 256) {
            int f = k0 + k;
            float v;
            if (f < 1024)       v = s0[f];
            else if (f < 2048)  v = s1[f - 1024];
            else                v = s2[f - 2048];
            sf[c][k] = v;
        }
    }
    __syncthreads();

    float s[CPB][4] = {};
    float comp[CPB][4] = {};
    const float* wcol = W1 + (size_t)k0 * 1024 + tid * 4;
    #pragma unroll 2
    for (int k = 0; k < 1536; k++) {
        float4 w = *(const float4*)(wcol + (size_t)k * 1024);
        float wv[4] = {w.x, w.y, w.z, w.w};
        #pragma unroll
        for (int c = 0; c < CPB; c++) {
            float f = sf[c][k];
            #pragma unroll
            for (int j = 0; j < 4; j++) {
                float p  = __fmul_rn(f, wv[j]);
                float e  = __fmaf_rn(f, wv[j], -p);
                float t  = __fadd_rn(s[c][j], p);
                float z  = __fsub_rn(t, s[c][j]);
                float e2 = __fadd_rn(__fsub_rn(s[c][j], __fsub_rn(t, z)),
                                     __fsub_rn(p, z));
                comp[c][j] = __fadd_rn(comp[c][j], __fadd_rn(e2, e));
                s[c][j] = t;
            }
        }
    }
    float* outs = g_hs[ks];
    float* outc = g_hc[ks];
    #pragma unroll
    for (int c = 0; c < CPB; c++) {
        int slot = slots[c];
        *(float4*)(outs + (size_t)slot*1024 + tid*4) =
            make_float4(s[c][0], s[c][1], s[c][2], s[c][3]);
        *(float4*)(outc + (size_t)slot*1024 + tid*4) =
            make_float4(comp[c][0], comp[c][1], comp[c][2], comp[c][3]);
    }
}

// =============================================================================
// K6: exact decisions — FLAGGED candidates only
// =============================================================================
__global__ __launch_bounds__(64) void k6_decide(const float* __restrict__ W2,
                                                const float* __restrict__ b2,
                                                const float* __restrict__ b1,
                                                const float* __restrict__ scores,
                                                const int*   __restrict__ connect)
{
    __shared__ double sh[1024];
    __shared__ double slog[NCLS];
    int gid = blockIdx.x;
    int b = gid >> 7, j = gid & (NCAND - 1);
    if (j >= g_fix_cnt[b]) return;
    int slot = b*NCAND + g_fix_list[b*NCAND + j];
    int tid = threadIdx.x;
    size_t base = (size_t)slot * 1024;
    for (int k = tid; k < 1024; k += 64) {
        double v = ((double)g_hs[0][base + k] + (double)g_hc[0][base + k])
                 + ((double)g_hs[1][base + k] + (double)g_hc[1][base + k])
                 + (double)b1[k];
        v = v > 0.0 ? v : 0.01 * v;
        sh[k] = v;
    }
    __syncthreads();

    if (tid < NCLS) {
        double acc = 0.0;
        #pragma unroll 8
        for (int k = 0; k < 1024; k++)
            acc = fma(sh[k], (double)W2[(size_t)k*NCLS + tid], acc);
        slog[tid] = acc + (double)b2[tid];
    }
    __syncthreads();

    if (tid == 0) {
        double m = slog[0];
        for (int c = 1; c < NCLS; c++) m = slog[c] > m ? slog[c] : m;
        double e[NCLS]; double ssum = 0.0;
        for (int c = 0; c < NCLS; c++) { e[c] = exp(slog[c] - m); ssum += e[c]; }
        double best = 0.0; int bl = 0;
        for (int c = 1; c < NCLS; c++) {
            double pr = e[c] / ssum;
            if (pr > best) { best = pr; bl = c; }
        }
        int p = g_cand_idx[slot];
        int si = connect[(size_t)b*2*NPAIR + p];
        int oi = connect[(size_t)b*2*NPAIR + NPAIR + p];
        double ov = best * (double)scores[b*NINST + si] * (double)scores[b*NINST + oi];
        g_cand_ovr[slot]  = ov;
        g_cand_prob[slot] = best;
        g_cand_lab[slot]  = bl;
    }
}

// =============================================================================
// K7: final top-100 per batch over NCAND candidates
// =============================================================================
__global__ __launch_bounds__(128) void k7_final(float* __restrict__ outbase)
{
    __shared__ double v[NCAND];
    __shared__ int    pix[NCAND];
    int b = blockIdx.x, tid = threadIdx.x;
    v[tid]   = g_cand_ovr[b*NCAND + tid];
    pix[tid] = g_cand_idx[b*NCAND + tid];
    __syncthreads();

    if (tid == 0) {
        float* out_lab  = outbase;
        float* out_prob = outbase + 800;
        float* out_val  = outbase + 1600;
        float* out_idx  = outbase + 2400;
        for (int t = 0; t < 100; t++) {
            double bv = -1.0; int bj = 0; int bidx = 0x7fffffff;
            for (int j = 0; j < NCAND; j++) {
                double val = v[j]; int ix = pix[j];
                if (val > bv || (val == bv && ix < bidx)) { bv = val; bj = j; bidx = ix; }
            }
            int slot2 = b*NCAND + bj;
            out_val [b*100 + t] = (float)bv;
            out_idx [b*100 + t] = (float)bidx;
            out_lab [b*100 + t] = (float)g_cand_lab[slot2];
            out_prob[b*100 + t] = (float)g_cand_prob[slot2];
            v[bj] = -2.0;
        }
    }
}

// =============================================================================
extern "C" void kernel_launch(void* const* d_in, const int* in_sizes, int n_in,
                              void* d_out, int out_size)
{
    const float* inst    = (const float*)d_in[0];
    const float* phrase  = (const float*)d_in[1];
    const float* scores  = (const float*)d_in[2];
    const float* W1      = (const float*)d_in[3];
    const float* b1      = (const float*)d_in[4];
    const float* W2      = (const float*)d_in[5];
    const float* b2      = (const float*)d_in[6];
    const int*   connect = (const int*)d_in[7];
    const int*   pidx    = (const int*)d_in[8];

    float* out        = (float*)d_out;
    float* out_logits = out;
    float* out_probs  = out + (size_t)BATCH*NPAIR*NCLS;
    float* out_top    = out + (size_t)2*BATCH*NPAIR*NCLS;

    cudaFuncSetAttribute(k2_mma, cudaFuncAttributeMaxDynamicSharedMemorySize, K2_SMEM);

    kprep_all<<<1088, 256>>>(W1, W2, b2, out_logits);
    kprep_a<<<NROWS, 256>>>(phrase, pidx);
    k1_instproj<<<dim3(32, 13), 256>>>(inst, W1);
    k2_mma<<<dim3(8, 78, BATCH), 256, K2_SMEM>>>(b1, connect, out_logits);
    k3b_softmax<<<(NROWS + 255) / 256, 256>>>(out_logits, scores, connect, out_probs);
    k4_select<<<BATCH, 1024>>>();
    k4b_flag<<<BATCH, NCAND>>>();
    k5_repair_h<<<dim3(2, 32, BATCH), 256>>>(inst, phrase, W1, connect, pidx);
    k6_decide<<<BATCH*NCAND, 64>>>(W2, b2, b1, scores, connect);
    k7_final<<<BATCH, 128>>>(out_top);
}

// round 16
// speedup vs baseline: 1.1325x; 1.0785x over previous
#include <cuda_runtime.h>
#include <cuda_bf16.h>
#include <cuda_fp16.h>
#include <math.h>
#include <stdint.h>

#define BATCH 8
#define NINST 100
#define NPAIR 9900
#define NCLS  51
#define NROWS (BATCH*NPAIR)   // 79200
#define NCAND 128
#define KC    32
#define MARGIN 2e-5f
// k2: CTA 128x128, 2 stages of 32KB (Ahi 8K | Alo 8K | Bhi 8K | Blo 8K), SW64.
#define K2A_LO 8192
#define K2B_HI 16384
#define K2B_LO 24576
#define K2STG  32768
#define SMEML_OFF (2*K2STG)                // 65536
#define K2_SMEM   (SMEML_OFF + 128*65*4)   // 98816  -> 2 CTAs/SM

// ---------------- scratch (device globals; no allocs allowed) ----------------
__device__ float  g_A12[BATCH*NINST*2048];
__device__ float  g_overall[NROWS];
__device__ float  g_predprob[NROWS];
__device__ float  g_margin[NROWS];
__device__ int    g_predlab[NROWS];
__device__ int    g_cand_idx[BATCH*NCAND];
__device__ int    g_cand_lab[BATCH*NCAND];
__device__ double g_cand_prob[BATCH*NCAND];
__device__ double g_cand_ovr[BATCH*NCAND];
__device__ int    g_fix_list[BATCH*NCAND];
__device__ int    g_fix_cnt[BATCH];
__device__ float  g_hs[2][BATCH*NCAND*1024];
__device__ float  g_hc[2][BATCH*NCAND*1024];
__device__ __align__(16) unsigned short g_Ahi[81100800];   // gathered phrase fp16 hi
__device__ __align__(16) unsigned short g_Alo[81100800];   // fp16 lo
__device__ __align__(16) unsigned short g_Bhi[1024*1024];  // W1c^T [n][k] fp16 hi
__device__ __align__(16) unsigned short g_Blo[1024*1024];  // fp16 lo
__device__ __align__(16) unsigned short g_W2fhi[64*1024];  // W2^T padded fp16 hi
__device__ __align__(16) unsigned short g_W2flo[64*1024];  // fp16 lo

// ---------------- helpers (baseline PTX only) ----------------
__device__ __forceinline__ uint32_t smem_u32(const void* p) {
    uint32_t a;
    asm("{ .reg .u64 t; cvta.to.shared.u64 t, %1; cvt.u32.u64 %0, t; }" : "=r"(a) : "l"(p));
    return a;
}
#define SWZ(x)   ((x) ^ (((x) >> 3) & 0x70))   // 128B-row swizzle
#define SWZ64(x) ((x) ^ (((x) >> 3) & 0x30))   // 64B-row swizzle
__device__ __forceinline__ void cpasync16(uint32_t dst, const void* src) {
    asm volatile("cp.async.cg.shared.global [%0], [%1], 16;" :: "r"(dst), "l"(src));
}
#define CP_COMMIT() asm volatile("cp.async.commit_group;" ::: "memory")
#define CP_WAIT(n)  asm volatile("cp.async.wait_group %0;" :: "n"(n) : "memory")
__device__ __forceinline__ void ldsm4(uint32_t* r, uint32_t addr) {
    asm volatile("ldmatrix.sync.aligned.m8n8.x4.shared.b16 {%0,%1,%2,%3}, [%4];"
        : "=r"(r[0]), "=r"(r[1]), "=r"(r[2]), "=r"(r[3]) : "r"(addr));
}
__device__ __forceinline__ void mma16816f(float* c, const uint32_t* a, const uint32_t* b) {
    asm volatile("mma.sync.aligned.m16n8k16.row.col.f32.f16.f16.f32 "
        "{%0,%1,%2,%3}, {%4,%5,%6,%7}, {%8,%9}, {%0,%1,%2,%3};"
        : "+f"(c[0]), "+f"(c[1]), "+f"(c[2]), "+f"(c[3])
        : "r"(a[0]), "r"(a[1]), "r"(a[2]), "r"(a[3]), "r"(b[0]), "r"(b[1]));
}
__device__ __forceinline__ uint32_t packh2(float x, float y) {
    __half2 t;
    t.x = __float2half_rn(x);
    t.y = __float2half_rn(y);
    return *(uint32_t*)&t;
}

// =============================================================================
// kprep_all: [0..1023] W1c -> g_Bhi/g_Blo; [1024..1087] W2 -> g_W2f* + init
// =============================================================================
__global__ __launch_bounds__(256) void kprep_all(const float* __restrict__ W1,
                                                 const float* __restrict__ W2,
                                                 const float* __restrict__ b2,
                                                 float* __restrict__ out_logits)
{
    int bid = blockIdx.x;
    if (bid < 1024) {
        __shared__ float t[32][33];
        int kk0 = (bid & 31) * 32, nn0 = (bid >> 5) * 32;
        int tx = threadIdx.x & 31, ty = threadIdx.x >> 5;
        #pragma unroll
        for (int i = 0; i < 32; i += 8)
            t[ty + i][tx] = W1[(size_t)(2048 + kk0 + ty + i) * 1024 + nn0 + tx];
        __syncthreads();
        #pragma unroll
        for (int i = 0; i < 32; i += 8) {
            float x = t[tx][ty + i];
            __half h = __float2half_rn(x);
            float lo = x - __half2float(h);
            size_t o = (size_t)(nn0 + ty + i) * 1024 + kk0 + tx;
            g_Bhi[o] = __half_as_ushort(h);
            g_Blo[o] = __half_as_ushort(__float2half_rn(lo));
        }
    } else {
        int n = bid - 1024;
        for (int k = threadIdx.x; k < 1024; k += 256) {
            float x = (n < NCLS) ? W2[(size_t)k * NCLS + n] : 0.f;
            __half h = __float2half_rn(x);
            float lo = x - __half2float(h);
            g_W2fhi[n * 1024 + k] = __half_as_ushort(h);
            g_W2flo[n * 1024 + k] = __half_as_ushort(__float2half_rn(lo));
        }
        for (int i = n * 256 + threadIdx.x; i < NROWS * NCLS; i += 64 * 256)
            out_logits[i] = b2[i % NCLS];
    }
}

// =============================================================================
// prep_a: gather phrase rows per pair, split into fp16 hi/lo
// =============================================================================
__global__ __launch_bounds__(256) void kprep_a(const float* __restrict__ phrase,
                                               const int* __restrict__ pidx)
{
    int r = blockIdx.x;
    int b = r / NPAIR;
    int ph = pidx[r];
    const float4* src = (const float4*)(phrase + ((size_t)b * NPAIR + ph) * 1024);
    float4 v = src[threadIdx.x];
    ushort4 hi, lo;
    #define SPL(c, hf, lf) { __half _h = __float2half_rn(v.c); \
        float _l = v.c - __half2float(_h); \
        hf = __half_as_ushort(_h); lf = __half_as_ushort(__float2half_rn(_l)); }
    SPL(x, hi.x, lo.x) SPL(y, hi.y, lo.y) SPL(z, hi.z, lo.z) SPL(w, hi.w, lo.w)
    #undef SPL
    size_t o = (size_t)r * 1024 + threadIdx.x * 4;
    *(ushort4*)(g_Ahi + o) = hi;
    *(ushort4*)(g_Alo + o) = lo;
}

// =============================================================================
// K1: A12[r, j] = inst[r, :] @ W1[half*1024 + :, jc]   (fp32, small)
// =============================================================================
__global__ __launch_bounds__(256) void k1_instproj(const float* __restrict__ inst,
                                                   const float* __restrict__ W1)
{
    __shared__ float As[16][68];
    __shared__ float Bs[16][64];
    int tid = threadIdx.x;
    int n0 = blockIdx.x * 64;
    int m0 = blockIdx.y * 64;
    int half = n0 >> 10;
    int jc0  = n0 & 1023;
    const float* wbase = W1 + (size_t)half * 1024 * 1024 + jc0;

    int arow = tid >> 2;
    int akq  = (tid & 3) * 4;
    int ar   = m0 + arow; if (ar > 799) ar = 799;
    const float* aptr = inst + (size_t)ar * 1024 + akq;
    int brow = tid >> 4;
    int bn   = (tid & 15) * 4;
    int tx = tid & 15, ty = tid >> 4;
    float acc[4][4] = {};

    for (int k0 = 0; k0 < 1024; k0 += 16) {
        float4 av = *(const float4*)(aptr + k0);
        float4 bv = *(const float4*)(wbase + (size_t)(k0 + brow) * 1024 + bn);
        As[akq+0][arow] = av.x; As[akq+1][arow] = av.y;
        As[akq+2][arow] = av.z; As[akq+3][arow] = av.w;
        *(float4*)&Bs[brow][bn] = bv;
        __syncthreads();
        #pragma unroll
        for (int kk = 0; kk < 16; kk++) {
            float af[4], bf[4];
            *(float4*)af = *(const float4*)&As[kk][ty*4];
            *(float4*)bf = *(const float4*)&Bs[kk][tx*4];
            #pragma unroll
            for (int i = 0; i < 4; i++)
                #pragma unroll
                for (int j = 0; j < 4; j++)
                    acc[i][j] += af[i] * bf[j];
        }
        __syncthreads();
    }
    #pragma unroll
    for (int i = 0; i < 4; i++) {
        int r = m0 + ty*4 + i;
        if (r < 800)
            *(float4*)&g_A12[(size_t)r*2048 + n0 + tx*4] =
                make_float4(acc[i][0], acc[i][1], acc[i][2], acc[i][3]);
    }
}

// =============================================================================
// K2 v9 (fused, fp16 3-prod, 2 CTA/SM, hoisted addressing):
// CTA 128x128, 256 thr (4M x 2N), KC=32 (SW64), 2 stages of 32KB.
// Each thread's load slots are fixed: rows (tid>>2, tid>>2+64), q=tid&3,
// identical swizzled dst offsets for A and B regions.
// =============================================================================
__global__ void __launch_bounds__(256, 2) k2_mma(const float* __restrict__ b1,
                                                 const int* __restrict__ connect,
                                                 float* __restrict__ out_logits)
{
    extern __shared__ __align__(1024) char smem[];
    uint32_t sb = smem_u32(smem);
    int tid = threadIdx.x;
    int lane = tid & 31, wid = tid >> 5;
    int wm = wid & 3, wn = wid >> 2;       // 4 M-warps x 2 N-warps
    int n0 = blockIdx.x * 128;
    int p0 = blockIdx.y * 128;
    int b  = blockIdx.z;
    size_t rowbase = (size_t)b * NPAIR;
    float* smemL = (float*)(smem + SMEML_OFF);

    for (int i = tid; i < 128*65; i += 256) smemL[i] = 0.f;

    // ---- hoisted load addressing (k0-invariant) ----
    int qv = tid & 3, rv = tid >> 2;                 // rv in [0,64)
    uint32_t d1 = SWZ64(rv * 64 + qv * 16);
    uint32_t d2 = SWZ64((rv + 64) * 64 + qv * 16);
    int pA1 = p0 + rv;       if (pA1 > NPAIR - 1) pA1 = NPAIR - 1;
    int pA2 = p0 + rv + 64;  if (pA2 > NPAIR - 1) pA2 = NPAIR - 1;
    size_t offA1 = (rowbase + pA1) * 1024 + qv * 8;
    size_t offA2 = (rowbase + pA2) * 1024 + qv * 8;
    size_t offB1 = (size_t)(n0 + rv) * 1024 + qv * 8;
    size_t offB2 = (size_t)(n0 + rv + 64) * 1024 + qv * 8;

    // ---- hoisted ldsm addressing ----
    int nrow  = (lane & 7) + ((lane >> 4) & 1) * 8;
    int khalf = ((lane >> 3) & 1) * 16;
    uint32_t offAm[2][2], offBn[2][4];
    #pragma unroll
    for (int ks = 0; ks < 2; ks++) {
        #pragma unroll
        for (int mt = 0; mt < 2; mt++)
            offAm[ks][mt] = SWZ64((wm*32 + mt*16 + (lane & 15)) * 64 + ks*32 + (lane >> 4) * 16);
        #pragma unroll
        for (int ntq = 0; ntq < 4; ntq++)
            offBn[ks][ntq] = SWZ64((wn*64 + ntq*16 + nrow) * 64 + ks*32 + khalf);
    }

    float acc[2][8][4] = {};

    #define K2LOAD(stg, kk) do { \
        uint32_t _st = (stg); int _k0 = (kk); \
        cpasync16(_st + d1,          g_Ahi + offA1 + _k0); \
        cpasync16(_st + d2,          g_Ahi + offA2 + _k0); \
        cpasync16(_st + K2A_LO + d1, g_Alo + offA1 + _k0); \
        cpasync16(_st + K2A_LO + d2, g_Alo + offA2 + _k0); \
        cpasync16(_st + K2B_HI + d1, g_Bhi + offB1 + _k0); \
        cpasync16(_st + K2B_HI + d2, g_Bhi + offB2 + _k0); \
        cpasync16(_st + K2B_LO + d1, g_Blo + offB1 + _k0); \
        cpasync16(_st + K2B_LO + d2, g_Blo + offB2 + _k0); \
    } while (0)

    K2LOAD(sb,         0);  CP_COMMIT();
    K2LOAD(sb + K2STG, KC); CP_COMMIT();

    #pragma unroll 1
    for (int c = 0; c < 32; c++) {
        if (c < 31) CP_WAIT(1);
        else        CP_WAIT(0);
        __syncthreads();

        uint32_t st  = sb + (c & 1) * K2STG;
        uint32_t sAh = st, sAl = st + K2A_LO, sBh = st + K2B_HI, sBl = st + K2B_LO;

        #pragma unroll
        for (int ks = 0; ks < 2; ks++) {
            uint32_t ah[2][4], al[2][4];
            #pragma unroll
            for (int mt = 0; mt < 2; mt++) {
                ldsm4(ah[mt], sAh + offAm[ks][mt]);
                ldsm4(al[mt], sAl + offAm[ks][mt]);
            }
            {   // hi*hi + lo*hi
                uint32_t bh[4][4];
                #pragma unroll
                for (int ntq = 0; ntq < 4; ntq++)
                    ldsm4(bh[ntq], sBh + offBn[ks][ntq]);
                #pragma unroll
                for (int mt = 0; mt < 2; mt++)
                    #pragma unroll
                    for (int nt = 0; nt < 8; nt++) {
                        const uint32_t* bhp = &bh[nt >> 1][(nt & 1) * 2];
                        mma16816f(acc[mt][nt], ah[mt], bhp);
                        mma16816f(acc[mt][nt], al[mt], bhp);
                    }
            }
            {   // hi*lo
                uint32_t bl[4][4];
                #pragma unroll
                for (int ntq = 0; ntq < 4; ntq++)
                    ldsm4(bl[ntq], sBl + offBn[ks][ntq]);
                #pragma unroll
                for (int mt = 0; mt < 2; mt++)
                    #pragma unroll
                    for (int nt = 0; nt < 8; nt++) {
                        const uint32_t* blp = &bl[nt >> 1][(nt & 1) * 2];
                        mma16816f(acc[mt][nt], ah[mt], blp);
                    }
            }
        }
        __syncthreads();
        if (c + 2 < 32) {
            K2LOAD(sb + (c & 1) * K2STG, (c + 2) * KC);
            CP_COMMIT();
        }
    }
    #undef K2LOAD

    // reuse stage-0 bytes for W2 tiles: [2 kinds][2 wnt][64n x 64k] SW128
    #pragma unroll 1
    for (int i = tid; i < 2048; i += 256) {
        int kind = i >> 10;
        int wnt  = (i >> 9) & 1;
        int n    = (i >> 3) & 63;
        int q    = i & 7;
        const unsigned short* src =
            (kind ? g_W2flo : g_W2fhi) + (size_t)n * 1024 + n0 + wnt * 64 + q * 8;
        uint32_t dst = sb + kind * 16384 + wnt * 8192 + SWZ(n * 128 + q * 16);
        cpasync16(dst, src);
    }
    CP_COMMIT();

    // ---- epilogue 1: gather-adds + lrelu (register-only) ----
    int gp = lane >> 2, tq = lane & 3;
    int n0w = n0 + wn * 64;
    size_t bb2 = (size_t)b * 2 * NPAIR;
    const float* a12b = g_A12 + (size_t)b * NINST * 2048;
    #pragma unroll
    for (int mt = 0; mt < 2; mt++) {
        #pragma unroll
        for (int half = 0; half < 2; half++) {
            int p = p0 + wm*32 + mt*16 + gp + half*8;
            if (p >= NPAIR) continue;
            int sub = connect[bb2 + p];
            int obj = connect[bb2 + NPAIR + p];
            const float* r1 = a12b + (size_t)sub * 2048 + n0w;
            const float* r2 = a12b + (size_t)obj * 2048 + 1024 + n0w;
            #pragma unroll
            for (int nt = 0; nt < 8; nt++) {
                int cc = nt*8 + tq*2;
                float2 v1 = *(const float2*)(r1 + cc);
                float2 v2 = *(const float2*)(r2 + cc);
                float2 vb = *(const float2*)(b1 + n0w + cc);
                float x = acc[mt][nt][half*2+0] + v1.x + v2.x + vb.x;
                float y = acc[mt][nt][half*2+1] + v1.y + v2.y + vb.y;
                acc[mt][nt][half*2+0] = x > 0.f ? x : 0.01f * x;
                acc[mt][nt][half*2+1] = y > 0.f ? y : 0.01f * y;
            }
        }
    }

    // ---- epilogue 2: pack h into fp16 hi/lo A-fragments (FA2 trick) ----
    uint32_t ahf[2][4][4], alf[2][4][4];
    #pragma unroll
    for (int mt = 0; mt < 2; mt++)
        #pragma unroll
        for (int j = 0; j < 4; j++)
            #pragma unroll
            for (int q = 0; q < 4; q++) {
                int nt = 2*j + (q >> 1);
                int ci = (q & 1) * 2;
                float x = acc[mt][nt][ci], y = acc[mt][nt][ci+1];
                uint32_t hp = packh2(x, y);
                __half2 hh = *(__half2*)&hp;
                ahf[mt][j][q] = hp;
                alf[mt][j][q] = packh2(x - __half2float(hh.x), y - __half2float(hh.y));
            }

    CP_WAIT(0);
    __syncthreads();

    // ---- epilogue 3: mini-GEMM h(32x64) @ W2(64k x 64n), 3 products ----
    uint32_t w2h = sb + wn * 8192;
    uint32_t w2l = sb + 16384 + wn * 8192;
    #pragma unroll
    for (int nh = 0; nh < 2; nh++) {
        float acc2[2][4][4] = {};
        #pragma unroll
        for (int j = 0; j < 4; j++) {
            int kb = j * 32;
            uint32_t bh[2][4], bl[2][4];
            #pragma unroll
            for (int ntq = 0; ntq < 2; ntq++) {
                uint32_t off = SWZ((nh*32 + ntq*16 + nrow) * 128 + kb + khalf);
                ldsm4(bh[ntq], w2h + off);
                ldsm4(bl[ntq], w2l + off);
            }
            #pragma unroll
            for (int mt = 0; mt < 2; mt++)
                #pragma unroll
                for (int nt = 0; nt < 4; nt++) {
                    const uint32_t* bhp = &bh[nt >> 1][(nt & 1) * 2];
                    const uint32_t* blp = &bl[nt >> 1][(nt & 1) * 2];
                    mma16816f(acc2[mt][nt], ahf[mt][j], bhp);
                    mma16816f(acc2[mt][nt], alf[mt][j], bhp);
                    mma16816f(acc2[mt][nt], ahf[mt][j], blp);
                }
        }
        #pragma unroll
        for (int mt = 0; mt < 2; mt++)
            #pragma unroll
            for (int nt = 0; nt < 4; nt++)
                #pragma unroll
                for (int ci = 0; ci < 4; ci++) {
                    int row = wm*32 + mt*16 + gp + (ci >> 1) * 8;
                    int col = nh*32 + nt*8 + tq*2 + (ci & 1);
                    atomicAdd(&smemL[row*65 + col], acc2[mt][nt][ci]);
                }
    }
    __syncthreads();

    // ---- epilogue 4: REDG partial logits into global ----
    #pragma unroll 1
    for (int i = tid; i < 128*64; i += 256) {
        int row = i >> 6, col = i & 63;
        int p = p0 + row;
        if (p < NPAIR && col < NCLS)
            atomicAdd(&out_logits[((size_t)b*NPAIR + p)*NCLS + col], smemL[row*65 + col]);
    }
}

// =============================================================================
// K3b: softmax -> probs; dense decisions + margins
// =============================================================================
__global__ void k3b_softmax(const float* __restrict__ out_logits,
                            const float* __restrict__ scores,
                            const int*   __restrict__ connect,
                            float* __restrict__ out_probs)
{
    int row = blockIdx.x * blockDim.x + threadIdx.x;
    if (row >= NROWS) return;
    const float* lp = out_logits + (size_t)row * NCLS;
    float l[NCLS];
    float m = -1e30f;
    #pragma unroll
    for (int c = 0; c < NCLS; c++) { l[c] = lp[c]; m = fmaxf(m, l[c]); }
    float s = 0.f;
    #pragma unroll
    for (int c = 0; c < NCLS; c++) { l[c] = expf(l[c] - m); s += l[c]; }
    float inv = 1.0f / s;
    float* pp = out_probs + (size_t)row * NCLS;
    float best = 0.f, second = 0.f; int bidx = 0;
    #pragma unroll
    for (int c = 0; c < NCLS; c++) {
        float pr = l[c] * inv;
        pp[c] = pr;
        if (c >= 1) {
            if (pr > best) { second = best; best = pr; bidx = c; }
            else if (pr > second) second = pr;
        }
    }
    int b = row / NPAIR, p = row % NPAIR;
    int si = connect[(size_t)b*2*NPAIR + p];
    int oi = connect[(size_t)b*2*NPAIR + NPAIR + p];
    g_overall[row]  = best * scores[b*NINST + si] * scores[b*NINST + oi];
    g_predprob[row] = best;
    g_predlab[row]  = bidx;
    g_margin[row]   = best - second;
}

// =============================================================================
// K4: warp-tournament top-NCAND selection
// =============================================================================
__global__ __launch_bounds__(1024) void k4_select()
{
    __shared__ float vals[NPAIR];
    __shared__ float wmax[32];
    __shared__ int   warg[32];
    __shared__ int   s_win;
    int b = blockIdx.x, tid = threadIdx.x, w = tid >> 5, lane = tid & 31;
    for (int i = tid; i < NPAIR; i += 1024) vals[i] = g_overall[b*NPAIR + i];
    __syncthreads();

    int lo = w * 310;
    int hiv = lo + 310; if (hiv > NPAIR) hiv = NPAIR;
    float bv = -1.f; int bi = 0x7fffffff;
    for (int i = lo + lane; i < hiv; i += 32) {
        float v = vals[i];
        if (v > bv || (v == bv && i < bi)) { bv = v; bi = i; }
    }
    #pragma unroll
    for (int o = 16; o; o >>= 1) {
        float ov = __shfl_down_sync(0xffffffffu, bv, o);
        int   oi = __shfl_down_sync(0xffffffffu, bi, o);
        if (ov > bv || (ov == bv && oi < bi)) { bv = ov; bi = oi; }
    }
    if (lane == 0) { wmax[w] = bv; warg[w] = bi; }
    __syncthreads();

    for (int t = 0; t < NCAND; t++) {
        if (tid < 32) {
            float v = wmax[lane]; int i2 = warg[lane];
            #pragma unroll
            for (int o = 16; o; o >>= 1) {
                float ov = __shfl_down_sync(0xffffffffu, v, o);
                int   oi = __shfl_down_sync(0xffffffffu, i2, o);
                if (ov > v || (ov == v && oi < i2)) { v = ov; i2 = oi; }
            }
            if (lane == 0) {
                g_cand_idx[b*NCAND + t] = i2;
                vals[i2] = -2.f;
                s_win = i2 / 310;
            }
        }
        __syncthreads();
        if (w == s_win) {
            float nv = -1.f; int ni = 0x7fffffff;
            for (int i = lo + lane; i < hiv; i += 32) {
                float v = vals[i];
                if (v > nv || (v == nv && i < ni)) { nv = v; ni = i; }
            }
            #pragma unroll
            for (int o = 16; o; o >>= 1) {
                float ov = __shfl_down_sync(0xffffffffu, nv, o);
                int   oi = __shfl_down_sync(0xffffffffu, ni, o);
                if (ov > nv || (ov == nv && oi < ni)) { nv = ov; ni = oi; }
            }
            if (lane == 0) { wmax[w] = nv; warg[w] = ni; }
        }
        __syncthreads();
    }
}

// =============================================================================
// K4b: init candidate outputs with dense values; flag decision-critical ones
// =============================================================================
__global__ __launch_bounds__(NCAND) void k4b_flag()
{
    __shared__ float ov[NCAND];
    __shared__ int   fl[NCAND];
    int b = blockIdx.x, i = threadIdx.x;
    int cand = g_cand_idx[b*NCAND + i];
    int row  = b*NPAIR + cand;
    float o  = g_overall[row];
    ov[i] = o;
    __syncthreads();

    int f = (g_margin[row] < MARGIN) ? 1 : 0;
    for (int j = 0; j < NCAND; j++)
        if (j != i && fabsf(o - ov[j]) < MARGIN) f = 1;
    fl[i] = f;

    g_cand_ovr [b*NCAND + i] = (double)o;
    g_cand_prob[b*NCAND + i] = (double)g_predprob[row];
    g_cand_lab [b*NCAND + i] = g_predlab[row];
    __syncthreads();

    if (i == 0) {
        int n = 0;
        for (int j = 0; j < NCAND; j++)
            if (fl[j]) g_fix_list[b*NCAND + (n++)] = j;
        g_fix_cnt[b] = n;
    }
}

// =============================================================================
// K5: compensated-fp32 exact partial h — FLAGGED candidates only
// =============================================================================
#define CPB 4
__global__ __launch_bounds__(256) void k5_repair_h(const float* __restrict__ inst,
                                                   const float* __restrict__ phrase,
                                                   const float* __restrict__ W1,
                                                   const int*   __restrict__ connect,
                                                   const int*   __restrict__ pidx)
{
    __shared__ float sf[CPB][1536];
    int ks = blockIdx.x;
    int g  = blockIdx.y;
    int b  = blockIdx.z;
    int tid = threadIdx.x;
    int k0 = ks * 1536;

    int cnt = g_fix_cnt[b];
    if (g * CPB >= cnt) return;
    int slots[CPB];

    #pragma unroll 1
    for (int c = 0; c < CPB; c++) {
        int jj = g*CPB + c; if (jj > cnt - 1) jj = cnt - 1;
        int slot = b*NCAND + g_fix_list[b*NCAND + jj];
        slots[c] = slot;
        int p  = g_cand_idx[slot];
        int si = connect[(size_t)b*2*NPAIR + p];
        int oi = connect[(size_t)b*2*NPAIR + NPAIR + p];
        int ph = pidx[b*NPAIR + p];
        const float* s0 = inst   + ((size_t)b*NINST + si)*1024;
        const float* s1 = inst   + ((size_t)b*NINST + oi)*1024;
        const float* s2 = phrase + ((size_t)b*NPAIR + ph)*1024;
        for (int k = tid; k < 1536; k += 256) {
            int f = k0 + k;
            float v;
            if (f < 1024)       v = s0[f];
            else if (f < 2048)  v = s1[f - 1024];
            else                v = s2[f - 2048];
            sf[c][k] = v;
        }
    }
    __syncthreads();

    float s[CPB][4] = {};
    float comp[CPB][4] = {};
    const float* wcol = W1 + (size_t)k0 * 1024 + tid * 4;
    #pragma unroll 2
    for (int k = 0; k < 1536; k++) {
        float4 w = *(const float4*)(wcol + (size_t)k * 1024);
        float wv[4] = {w.x, w.y, w.z, w.w};
        #pragma unroll
        for (int c = 0; c < CPB; c++) {
            float f = sf[c][k];
            #pragma unroll
            for (int j = 0; j < 4; j++) {
                float p  = __fmul_rn(f, wv[j]);
                float e  = __fmaf_rn(f, wv[j], -p);
                float t  = __fadd_rn(s[c][j], p);
                float z  = __fsub_rn(t, s[c][j]);
                float e2 = __fadd_rn(__fsub_rn(s[c][j], __fsub_rn(t, z)),
                                     __fsub_rn(p, z));
                comp[c][j] = __fadd_rn(comp[c][j], __fadd_rn(e2, e));
                s[c][j] = t;
            }
        }
    }
    float* outs = g_hs[ks];
    float* outc = g_hc[ks];
    #pragma unroll
    for (int c = 0; c < CPB; c++) {
        int slot = slots[c];
        *(float4*)(outs + (size_t)slot*1024 + tid*4) =
            make_float4(s[c][0], s[c][1], s[c][2], s[c][3]);
        *(float4*)(outc + (size_t)slot*1024 + tid*4) =
            make_float4(comp[c][0], comp[c][1], comp[c][2], comp[c][3]);
    }
}

// =============================================================================
// K6: exact decisions — FLAGGED candidates only
// =============================================================================
__global__ __launch_bounds__(64) void k6_decide(const float* __restrict__ W2,
                                                const float* __restrict__ b2,
                                                const float* __restrict__ b1,
                                                const float* __restrict__ scores,
                                                const int*   __restrict__ connect)
{
    __shared__ double sh[1024];
    __shared__ double slog[NCLS];
    int gid = blockIdx.x;
    int b = gid >> 7, j = gid & (NCAND - 1);
    if (j >= g_fix_cnt[b]) return;
    int slot = b*NCAND + g_fix_list[b*NCAND + j];
    int tid = threadIdx.x;
    size_t base = (size_t)slot * 1024;
    for (int k = tid; k < 1024; k += 64) {
        double v = ((double)g_hs[0][base + k] + (double)g_hc[0][base + k])
                 + ((double)g_hs[1][base + k] + (double)g_hc[1][base + k])
                 + (double)b1[k];
        v = v > 0.0 ? v : 0.01 * v;
        sh[k] = v;
    }
    __syncthreads();

    if (tid < NCLS) {
        double acc = 0.0;
        #pragma unroll 8
        for (int k = 0; k < 1024; k++)
            acc = fma(sh[k], (double)W2[(size_t)k*NCLS + tid], acc);
        slog[tid] = acc + (double)b2[tid];
    }
    __syncthreads();

    if (tid == 0) {
        double m = slog[0];
        for (int c = 1; c < NCLS; c++) m = slog[c] > m ? slog[c] : m;
        double e[NCLS]; double ssum = 0.0;
        for (int c = 0; c < NCLS; c++) { e[c] = exp(slog[c] - m); ssum += e[c]; }
        double best = 0.0; int bl = 0;
        for (int c = 1; c < NCLS; c++) {
            double pr = e[c] / ssum;
            if (pr > best) { best = pr; bl = c; }
        }
        int p = g_cand_idx[slot];
        int si = connect[(size_t)b*2*NPAIR + p];
        int oi = connect[(size_t)b*2*NPAIR + NPAIR + p];
        double ov = best * (double)scores[b*NINST + si] * (double)scores[b*NINST + oi];
        g_cand_ovr[slot]  = ov;
        g_cand_prob[slot] = best;
        g_cand_lab[slot]  = bl;
    }
}

// =============================================================================
// K7: final top-100 per batch over NCAND candidates
// =============================================================================
__global__ __launch_bounds__(128) void k7_final(float* __restrict__ outbase)
{
    __shared__ double v[NCAND];
    __shared__ int    pix[NCAND];
    int b = blockIdx.x, tid = threadIdx.x;
    v[tid]   = g_cand_ovr[b*NCAND + tid];
    pix[tid] = g_cand_idx[b*NCAND + tid];
    __syncthreads();

    if (tid == 0) {
        float* out_lab  = outbase;
        float* out_prob = outbase + 800;
        float* out_val  = outbase + 1600;
        float* out_idx  = outbase + 2400;
        for (int t = 0; t < 100; t++) {
            double bv = -1.0; int bj = 0; int bidx = 0x7fffffff;
            for (int j = 0; j < NCAND; j++) {
                double val = v[j]; int ix = pix[j];
                if (val > bv || (val == bv && ix < bidx)) { bv = val; bj = j; bidx = ix; }
            }
            int slot2 = b*NCAND + bj;
            out_val [b*100 + t] = (float)bv;
            out_idx [b*100 + t] = (float)bidx;
            out_lab [b*100 + t] = (float)g_cand_lab[slot2];
            out_prob[b*100 + t] = (float)g_cand_prob[slot2];
            v[bj] = -2.0;
        }
    }
}

// =============================================================================
extern "C" void kernel_launch(void* const* d_in, const int* in_sizes, int n_in,
                              void* d_out, int out_size)
{
    const float* inst    = (const float*)d_in[0];
    const float* phrase  = (const float*)d_in[1];
    const float* scores  = (const float*)d_in[2];
    const float* W1      = (const float*)d_in[3];
    const float* b1      = (const float*)d_in[4];
    const float* W2      = (const float*)d_in[5];
    const float* b2      = (const float*)d_in[6];
    const int*   connect = (const int*)d_in[7];
    const int*   pidx    = (const int*)d_in[8];

    float* out        = (float*)d_out;
    float* out_logits = out;
    float* out_probs  = out + (size_t)BATCH*NPAIR*NCLS;
    float* out_top    = out + (size_t)2*BATCH*NPAIR*NCLS;

    cudaFuncSetAttribute(k2_mma, cudaFuncAttributeMaxDynamicSharedMemorySize, K2_SMEM);

    kprep_all<<<1088, 256>>>(W1, W2, b2, out_logits);
    kprep_a<<<NROWS, 256>>>(phrase, pidx);
    k1_instproj<<<dim3(32, 13), 256>>>(inst, W1);
    k2_mma<<<dim3(8, 78, BATCH), 256, K2_SMEM>>>(b1, connect, out_logits);
    k3b_softmax<<<(NROWS + 255) / 256, 256>>>(out_logits, scores, connect, out_probs);
    k4_select<<<BATCH, 1024>>>();
    k4b_flag<<<BATCH, NCAND>>>();
    k5_repair_h<<<dim3(2, 32, BATCH), 256>>>(inst, phrase, W1, connect, pidx);
    k6_decide<<<BATCH*NCAND, 64>>>(W2, b2, b1, scores, connect);
    k7_final<<<BATCH, 128>>>(out_top);
}

// round 17
// speedup vs baseline: 1.1387x; 1.0054x over previous
#include <cuda_runtime.h>
#include <cuda_bf16.h>
#include <cuda_fp16.h>
#include <math.h>
#include <stdint.h>

#define BATCH 8
#define NINST 100
#define NPAIR 9900
#define NCLS  51
#define NROWS (BATCH*NPAIR)   // 79200
#define NCAND 128
#define KC    32
#define MARGIN_LBL 2e-5f      // argmax prob-gap flag threshold
#define MARGIN_OVR 6e-6f      // pairwise overall-gap flag threshold (~8 sigma)
// k2: CTA 128x128, 2 stages of 32KB (Ahi 8K | Alo 8K | Bhi 8K | Blo 8K), SW64.
#define K2A_LO 8192
#define K2B_HI 16384
#define K2B_LO 24576
#define K2STG  32768
#define SMEML_OFF (2*K2STG)                // 65536
#define K2_SMEM   (SMEML_OFF + 128*65*4)   // 98816  -> 2 CTAs/SM

// ---------------- scratch (device globals; no allocs allowed) ----------------
__device__ float  g_A12[BATCH*NINST*2048];
__device__ float  g_overall[NROWS];
__device__ float  g_predprob[NROWS];
__device__ float  g_margin[NROWS];
__device__ int    g_predlab[NROWS];
__device__ int    g_cand_idx[BATCH*NCAND];
__device__ int    g_cand_lab[BATCH*NCAND];
__device__ double g_cand_prob[BATCH*NCAND];
__device__ double g_cand_ovr[BATCH*NCAND];
__device__ int    g_fix_list[BATCH*NCAND];
__device__ int    g_fix_cnt[BATCH];
__device__ float  g_hs[2][BATCH*NCAND*1024];
__device__ float  g_hc[2][BATCH*NCAND*1024];
__device__ __align__(16) unsigned short g_Ahi[81100800];   // gathered phrase fp16 hi
__device__ __align__(16) unsigned short g_Alo[81100800];   // fp16 lo
__device__ __align__(16) unsigned short g_Bhi[1024*1024];  // W1c^T [n][k] fp16 hi
__device__ __align__(16) unsigned short g_Blo[1024*1024];  // fp16 lo
__device__ __align__(16) unsigned short g_W2fhi[64*1024];  // W2^T padded fp16 hi
__device__ __align__(16) unsigned short g_W2flo[64*1024];  // fp16 lo

// ---------------- helpers (baseline PTX only) ----------------
__device__ __forceinline__ uint32_t smem_u32(const void* p) {
    uint32_t a;
    asm("{ .reg .u64 t; cvta.to.shared.u64 t, %1; cvt.u32.u64 %0, t; }" : "=r"(a) : "l"(p));
    return a;
}
#define SWZ(x)   ((x) ^ (((x) >> 3) & 0x70))   // 128B-row swizzle
#define SWZ64(x) ((x) ^ (((x) >> 3) & 0x30))   // 64B-row swizzle
__device__ __forceinline__ void cpasync16(uint32_t dst, const void* src) {
    asm volatile("cp.async.cg.shared.global [%0], [%1], 16;" :: "r"(dst), "l"(src));
}
#define CP_COMMIT() asm volatile("cp.async.commit_group;" ::: "memory")
#define CP_WAIT(n)  asm volatile("cp.async.wait_group %0;" :: "n"(n) : "memory")
__device__ __forceinline__ void ldsm4(uint32_t* r, uint32_t addr) {
    asm volatile("ldmatrix.sync.aligned.m8n8.x4.shared.b16 {%0,%1,%2,%3}, [%4];"
        : "=r"(r[0]), "=r"(r[1]), "=r"(r[2]), "=r"(r[3]) : "r"(addr));
}
__device__ __forceinline__ void mma16816f(float* c, const uint32_t* a, const uint32_t* b) {
    asm volatile("mma.sync.aligned.m16n8k16.row.col.f32.f16.f16.f32 "
        "{%0,%1,%2,%3}, {%4,%5,%6,%7}, {%8,%9}, {%0,%1,%2,%3};"
        : "+f"(c[0]), "+f"(c[1]), "+f"(c[2]), "+f"(c[3])
        : "r"(a[0]), "r"(a[1]), "r"(a[2]), "r"(a[3]), "r"(b[0]), "r"(b[1]));
}
__device__ __forceinline__ uint32_t packh2(float x, float y) {
    __half2 t;
    t.x = __float2half_rn(x);
    t.y = __float2half_rn(y);
    return *(uint32_t*)&t;
}

// =============================================================================
// kprep_all: [0..1023] W1c -> g_Bhi/g_Blo; [1024..1087] W2 -> g_W2f* + init
// =============================================================================
__global__ __launch_bounds__(256) void kprep_all(const float* __restrict__ W1,
                                                 const float* __restrict__ W2,
                                                 const float* __restrict__ b2,
                                                 float* __restrict__ out_logits)
{
    int bid = blockIdx.x;
    if (bid < 1024) {
        __shared__ float t[32][33];
        int kk0 = (bid & 31) * 32, nn0 = (bid >> 5) * 32;
        int tx = threadIdx.x & 31, ty = threadIdx.x >> 5;
        #pragma unroll
        for (int i = 0; i < 32; i += 8)
            t[ty + i][tx] = W1[(size_t)(2048 + kk0 + ty + i) * 1024 + nn0 + tx];
        __syncthreads();
        #pragma unroll
        for (int i = 0; i < 32; i += 8) {
            float x = t[tx][ty + i];
            __half h = __float2half_rn(x);
            float lo = x - __half2float(h);
            size_t o = (size_t)(nn0 + ty + i) * 1024 + kk0 + tx;
            g_Bhi[o] = __half_as_ushort(h);
            g_Blo[o] = __half_as_ushort(__float2half_rn(lo));
        }
    } else {
        int n = bid - 1024;
        for (int k = threadIdx.x; k < 1024; k += 256) {
            float x = (n < NCLS) ? W2[(size_t)k * NCLS + n] : 0.f;
            __half h = __float2half_rn(x);
            float lo = x - __half2float(h);
            g_W2fhi[n * 1024 + k] = __half_as_ushort(h);
            g_W2flo[n * 1024 + k] = __half_as_ushort(__float2half_rn(lo));
        }
        for (int i = n * 256 + threadIdx.x; i < NROWS * NCLS; i += 64 * 256)
            out_logits[i] = b2[i % NCLS];
    }
}

// =============================================================================
// prep_a: gather phrase rows per pair, split into fp16 hi/lo
// =============================================================================
__global__ __launch_bounds__(256) void kprep_a(const float* __restrict__ phrase,
                                               const int* __restrict__ pidx)
{
    int r = blockIdx.x;
    int b = r / NPAIR;
    int ph = pidx[r];
    const float4* src = (const float4*)(phrase + ((size_t)b * NPAIR + ph) * 1024);
    float4 v = src[threadIdx.x];
    ushort4 hi, lo;
    #define SPL(c, hf, lf) { __half _h = __float2half_rn(v.c); \
        float _l = v.c - __half2float(_h); \
        hf = __half_as_ushort(_h); lf = __half_as_ushort(__float2half_rn(_l)); }
    SPL(x, hi.x, lo.x) SPL(y, hi.y, lo.y) SPL(z, hi.z, lo.z) SPL(w, hi.w, lo.w)
    #undef SPL
    size_t o = (size_t)r * 1024 + threadIdx.x * 4;
    *(ushort4*)(g_Ahi + o) = hi;
    *(ushort4*)(g_Alo + o) = lo;
}

// =============================================================================
// K1: A12[r, j] = inst[r, :] @ W1[half*1024 + :, jc]   (fp32, small)
// =============================================================================
__global__ __launch_bounds__(256) void k1_instproj(const float* __restrict__ inst,
                                                   const float* __restrict__ W1)
{
    __shared__ float As[16][68];
    __shared__ float Bs[16][64];
    int tid = threadIdx.x;
    int n0 = blockIdx.x * 64;
    int m0 = blockIdx.y * 64;
    int half = n0 >> 10;
    int jc0  = n0 & 1023;
    const float* wbase = W1 + (size_t)half * 1024 * 1024 + jc0;

    int arow = tid >> 2;
    int akq  = (tid & 3) * 4;
    int ar   = m0 + arow; if (ar > 799) ar = 799;
    const float* aptr = inst + (size_t)ar * 1024 + akq;
    int brow = tid >> 4;
    int bn   = (tid & 15) * 4;
    int tx = tid & 15, ty = tid >> 4;
    float acc[4][4] = {};

    for (int k0 = 0; k0 < 1024; k0 += 16) {
        float4 av = *(const float4*)(aptr + k0);
        float4 bv = *(const float4*)(wbase + (size_t)(k0 + brow) * 1024 + bn);
        As[akq+0][arow] = av.x; As[akq+1][arow] = av.y;
        As[akq+2][arow] = av.z; As[akq+3][arow] = av.w;
        *(float4*)&Bs[brow][bn] = bv;
        __syncthreads();
        #pragma unroll
        for (int kk = 0; kk < 16; kk++) {
            float af[4], bf[4];
            *(float4*)af = *(const float4*)&As[kk][ty*4];
            *(float4*)bf = *(const float4*)&Bs[kk][tx*4];
            #pragma unroll
            for (int i = 0; i < 4; i++)
                #pragma unroll
                for (int j = 0; j < 4; j++)
                    acc[i][j] += af[i] * bf[j];
        }
        __syncthreads();
    }
    #pragma unroll
    for (int i = 0; i < 4; i++) {
        int r = m0 + ty*4 + i;
        if (r < 800)
            *(float4*)&g_A12[(size_t)r*2048 + n0 + tx*4] =
                make_float4(acc[i][0], acc[i][1], acc[i][2], acc[i][3]);
    }
}

// =============================================================================
// K2 v9 (fused, fp16 3-prod, 2 CTA/SM, hoisted addressing)
// =============================================================================
__global__ void __launch_bounds__(256, 2) k2_mma(const float* __restrict__ b1,
                                                 const int* __restrict__ connect,
                                                 float* __restrict__ out_logits)
{
    extern __shared__ __align__(1024) char smem[];
    uint32_t sb = smem_u32(smem);
    int tid = threadIdx.x;
    int lane = tid & 31, wid = tid >> 5;
    int wm = wid & 3, wn = wid >> 2;       // 4 M-warps x 2 N-warps
    int n0 = blockIdx.x * 128;
    int p0 = blockIdx.y * 128;
    int b  = blockIdx.z;
    size_t rowbase = (size_t)b * NPAIR;
    float* smemL = (float*)(smem + SMEML_OFF);

    for (int i = tid; i < 128*65; i += 256) smemL[i] = 0.f;

    // ---- hoisted load addressing (k0-invariant) ----
    int qv = tid & 3, rv = tid >> 2;
    uint32_t d1 = SWZ64(rv * 64 + qv * 16);
    uint32_t d2 = SWZ64((rv + 64) * 64 + qv * 16);
    int pA1 = p0 + rv;       if (pA1 > NPAIR - 1) pA1 = NPAIR - 1;
    int pA2 = p0 + rv + 64;  if (pA2 > NPAIR - 1) pA2 = NPAIR - 1;
    size_t offA1 = (rowbase + pA1) * 1024 + qv * 8;
    size_t offA2 = (rowbase + pA2) * 1024 + qv * 8;
    size_t offB1 = (size_t)(n0 + rv) * 1024 + qv * 8;
    size_t offB2 = (size_t)(n0 + rv + 64) * 1024 + qv * 8;

    // ---- hoisted ldsm addressing ----
    int nrow  = (lane & 7) + ((lane >> 4) & 1) * 8;
    int khalf = ((lane >> 3) & 1) * 16;
    uint32_t offAm[2][2], offBn[2][4];
    #pragma unroll
    for (int ks = 0; ks < 2; ks++) {
        #pragma unroll
        for (int mt = 0; mt < 2; mt++)
            offAm[ks][mt] = SWZ64((wm*32 + mt*16 + (lane & 15)) * 64 + ks*32 + (lane >> 4) * 16);
        #pragma unroll
        for (int ntq = 0; ntq < 4; ntq++)
            offBn[ks][ntq] = SWZ64((wn*64 + ntq*16 + nrow) * 64 + ks*32 + khalf);
    }

    float acc[2][8][4] = {};

    #define K2LOAD(stg, kk) do { \
        uint32_t _st = (stg); int _k0 = (kk); \
        cpasync16(_st + d1,          g_Ahi + offA1 + _k0); \
        cpasync16(_st + d2,          g_Ahi + offA2 + _k0); \
        cpasync16(_st + K2A_LO + d1, g_Alo + offA1 + _k0); \
        cpasync16(_st + K2A_LO + d2, g_Alo + offA2 + _k0); \
        cpasync16(_st + K2B_HI + d1, g_Bhi + offB1 + _k0); \
        cpasync16(_st + K2B_HI + d2, g_Bhi + offB2 + _k0); \
        cpasync16(_st + K2B_LO + d1, g_Blo + offB1 + _k0); \
        cpasync16(_st + K2B_LO + d2, g_Blo + offB2 + _k0); \
    } while (0)

    K2LOAD(sb,         0);  CP_COMMIT();
    K2LOAD(sb + K2STG, KC); CP_COMMIT();

    #pragma unroll 1
    for (int c = 0; c < 32; c++) {
        if (c < 31) CP_WAIT(1);
        else        CP_WAIT(0);
        __syncthreads();

        uint32_t st  = sb + (c & 1) * K2STG;
        uint32_t sAh = st, sAl = st + K2A_LO, sBh = st + K2B_HI, sBl = st + K2B_LO;

        #pragma unroll
        for (int ks = 0; ks < 2; ks++) {
            uint32_t ah[2][4], al[2][4];
            #pragma unroll
            for (int mt = 0; mt < 2; mt++) {
                ldsm4(ah[mt], sAh + offAm[ks][mt]);
                ldsm4(al[mt], sAl + offAm[ks][mt]);
            }
            {   // hi*hi + lo*hi
                uint32_t bh[4][4];
                #pragma unroll
                for (int ntq = 0; ntq < 4; ntq++)
                    ldsm4(bh[ntq], sBh + offBn[ks][ntq]);
                #pragma unroll
                for (int mt = 0; mt < 2; mt++)
                    #pragma unroll
                    for (int nt = 0; nt < 8; nt++) {
                        const uint32_t* bhp = &bh[nt >> 1][(nt & 1) * 2];
                        mma16816f(acc[mt][nt], ah[mt], bhp);
                        mma16816f(acc[mt][nt], al[mt], bhp);
                    }
            }
            {   // hi*lo
                uint32_t bl[4][4];
                #pragma unroll
                for (int ntq = 0; ntq < 4; ntq++)
                    ldsm4(bl[ntq], sBl + offBn[ks][ntq]);
                #pragma unroll
                for (int mt = 0; mt < 2; mt++)
                    #pragma unroll
                    for (int nt = 0; nt < 8; nt++) {
                        const uint32_t* blp = &bl[nt >> 1][(nt & 1) * 2];
                        mma16816f(acc[mt][nt], ah[mt], blp);
                    }
            }
        }
        __syncthreads();
        if (c + 2 < 32) {
            K2LOAD(sb + (c & 1) * K2STG, (c + 2) * KC);
            CP_COMMIT();
        }
    }
    #undef K2LOAD

    // reuse stage-0 bytes for W2 tiles: [2 kinds][2 wnt][64n x 64k] SW128
    #pragma unroll 1
    for (int i = tid; i < 2048; i += 256) {
        int kind = i >> 10;
        int wnt  = (i >> 9) & 1;
        int n    = (i >> 3) & 63;
        int q    = i & 7;
        const unsigned short* src =
            (kind ? g_W2flo : g_W2fhi) + (size_t)n * 1024 + n0 + wnt * 64 + q * 8;
        uint32_t dst = sb + kind * 16384 + wnt * 8192 + SWZ(n * 128 + q * 16);
        cpasync16(dst, src);
    }
    CP_COMMIT();

    // ---- epilogue 1: gather-adds + lrelu (register-only) ----
    int gp = lane >> 2, tq = lane & 3;
    int n0w = n0 + wn * 64;
    size_t bb2 = (size_t)b * 2 * NPAIR;
    const float* a12b = g_A12 + (size_t)b * NINST * 2048;
    #pragma unroll
    for (int mt = 0; mt < 2; mt++) {
        #pragma unroll
        for (int half = 0; half < 2; half++) {
            int p = p0 + wm*32 + mt*16 + gp + half*8;
            if (p >= NPAIR) continue;
            int sub = connect[bb2 + p];
            int obj = connect[bb2 + NPAIR + p];
            const float* r1 = a12b + (size_t)sub * 2048 + n0w;
            const float* r2 = a12b + (size_t)obj * 2048 + 1024 + n0w;
            #pragma unroll
            for (int nt = 0; nt < 8; nt++) {
                int cc = nt*8 + tq*2;
                float2 v1 = *(const float2*)(r1 + cc);
                float2 v2 = *(const float2*)(r2 + cc);
                float2 vb = *(const float2*)(b1 + n0w + cc);
                float x = acc[mt][nt][half*2+0] + v1.x + v2.x + vb.x;
                float y = acc[mt][nt][half*2+1] + v1.y + v2.y + vb.y;
                acc[mt][nt][half*2+0] = x > 0.f ? x : 0.01f * x;
                acc[mt][nt][half*2+1] = y > 0.f ? y : 0.01f * y;
            }
        }
    }

    // ---- epilogue 2: pack h into fp16 hi/lo A-fragments (FA2 trick) ----
    uint32_t ahf[2][4][4], alf[2][4][4];
    #pragma unroll
    for (int mt = 0; mt < 2; mt++)
        #pragma unroll
        for (int j = 0; j < 4; j++)
            #pragma unroll
            for (int q = 0; q < 4; q++) {
                int nt = 2*j + (q >> 1);
                int ci = (q & 1) * 2;
                float x = acc[mt][nt][ci], y = acc[mt][nt][ci+1];
                uint32_t hp = packh2(x, y);
                __half2 hh = *(__half2*)&hp;
                ahf[mt][j][q] = hp;
                alf[mt][j][q] = packh2(x - __half2float(hh.x), y - __half2float(hh.y));
            }

    CP_WAIT(0);
    __syncthreads();

    // ---- epilogue 3: mini-GEMM h(32x64) @ W2(64k x 64n), 3 products ----
    uint32_t w2h = sb + wn * 8192;
    uint32_t w2l = sb + 16384 + wn * 8192;
    #pragma unroll
    for (int nh = 0; nh < 2; nh++) {
        float acc2[2][4][4] = {};
        #pragma unroll
        for (int j = 0; j < 4; j++) {
            int kb = j * 32;
            uint32_t bh[2][4], bl[2][4];
            #pragma unroll
            for (int ntq = 0; ntq < 2; ntq++) {
                uint32_t off = SWZ((nh*32 + ntq*16 + nrow) * 128 + kb + khalf);
                ldsm4(bh[ntq], w2h + off);
                ldsm4(bl[ntq], w2l + off);
            }
            #pragma unroll
            for (int mt = 0; mt < 2; mt++)
                #pragma unroll
                for (int nt = 0; nt < 4; nt++) {
                    const uint32_t* bhp = &bh[nt >> 1][(nt & 1) * 2];
                    const uint32_t* blp = &bl[nt >> 1][(nt & 1) * 2];
                    mma16816f(acc2[mt][nt], ahf[mt][j], bhp);
                    mma16816f(acc2[mt][nt], alf[mt][j], bhp);
                    mma16816f(acc2[mt][nt], ahf[mt][j], blp);
                }
        }
        #pragma unroll
        for (int mt = 0; mt < 2; mt++)
            #pragma unroll
            for (int nt = 0; nt < 4; nt++)
                #pragma unroll
                for (int ci = 0; ci < 4; ci++) {
                    int row = wm*32 + mt*16 + gp + (ci >> 1) * 8;
                    int col = nh*32 + nt*8 + tq*2 + (ci & 1);
                    atomicAdd(&smemL[row*65 + col], acc2[mt][nt][ci]);
                }
    }
    __syncthreads();

    // ---- epilogue 4: REDG partial logits into global ----
    #pragma unroll 1
    for (int i = tid; i < 128*64; i += 256) {
        int row = i >> 6, col = i & 63;
        int p = p0 + row;
        if (p < NPAIR && col < NCLS)
            atomicAdd(&out_logits[((size_t)b*NPAIR + p)*NCLS + col], smemL[row*65 + col]);
    }
}

// =============================================================================
// K3b: softmax -> probs; dense decisions + margins
// =============================================================================
__global__ void k3b_softmax(const float* __restrict__ out_logits,
                            const float* __restrict__ scores,
                            const int*   __restrict__ connect,
                            float* __restrict__ out_probs)
{
    int row = blockIdx.x * blockDim.x + threadIdx.x;
    if (row >= NROWS) return;
    const float* lp = out_logits + (size_t)row * NCLS;
    float l[NCLS];
    float m = -1e30f;
    #pragma unroll
    for (int c = 0; c < NCLS; c++) { l[c] = lp[c]; m = fmaxf(m, l[c]); }
    float s = 0.f;
    #pragma unroll
    for (int c = 0; c < NCLS; c++) { l[c] = expf(l[c] - m); s += l[c]; }
    float inv = 1.0f / s;
    float* pp = out_probs + (size_t)row * NCLS;
    float best = 0.f, second = 0.f; int bidx = 0;
    #pragma unroll
    for (int c = 0; c < NCLS; c++) {
        float pr = l[c] * inv;
        pp[c] = pr;
        if (c >= 1) {
            if (pr > best) { second = best; best = pr; bidx = c; }
            else if (pr > second) second = pr;
        }
    }
    int b = row / NPAIR, p = row % NPAIR;
    int si = connect[(size_t)b*2*NPAIR + p];
    int oi = connect[(size_t)b*2*NPAIR + NPAIR + p];
    g_overall[row]  = best * scores[b*NINST + si] * scores[b*NINST + oi];
    g_predprob[row] = best;
    g_predlab[row]  = bidx;
    g_margin[row]   = best - second;
}

// =============================================================================
// K4: warp-tournament top-NCAND selection
// =============================================================================
__global__ __launch_bounds__(1024) void k4_select()
{
    __shared__ float vals[NPAIR];
    __shared__ float wmax[32];
    __shared__ int   warg[32];
    __shared__ int   s_win;
    int b = blockIdx.x, tid = threadIdx.x, w = tid >> 5, lane = tid & 31;
    for (int i = tid; i < NPAIR; i += 1024) vals[i] = g_overall[b*NPAIR + i];
    __syncthreads();

    int lo = w * 310;
    int hiv = lo + 310; if (hiv > NPAIR) hiv = NPAIR;
    float bv = -1.f; int bi = 0x7fffffff;
    for (int i = lo + lane; i < hiv; i += 32) {
        float v = vals[i];
        if (v > bv || (v == bv && i < bi)) { bv = v; bi = i; }
    }
    #pragma unroll
    for (int o = 16; o; o >>= 1) {
        float ov = __shfl_down_sync(0xffffffffu, bv, o);
        int   oi = __shfl_down_sync(0xffffffffu, bi, o);
        if (ov > bv || (ov == bv && oi < bi)) { bv = ov; bi = oi; }
    }
    if (lane == 0) { wmax[w] = bv; warg[w] = bi; }
    __syncthreads();

    for (int t = 0; t < NCAND; t++) {
        if (tid < 32) {
            float v = wmax[lane]; int i2 = warg[lane];
            #pragma unroll
            for (int o = 16; o; o >>= 1) {
                float ov = __shfl_down_sync(0xffffffffu, v, o);
                int   oi = __shfl_down_sync(0xffffffffu, i2, o);
                if (ov > v || (ov == v && oi < i2)) { v = ov; i2 = oi; }
            }
            if (lane == 0) {
                g_cand_idx[b*NCAND + t] = i2;
                vals[i2] = -2.f;
                s_win = i2 / 310;
            }
        }
        __syncthreads();
        if (w == s_win) {
            float nv = -1.f; int ni = 0x7fffffff;
            for (int i = lo + lane; i < hiv; i += 32) {
                float v = vals[i];
                if (v > nv || (v == nv && i < ni)) { nv = v; ni = i; }
            }
            #pragma unroll
            for (int o = 16; o; o >>= 1) {
                float ov = __shfl_down_sync(0xffffffffu, nv, o);
                int   oi = __shfl_down_sync(0xffffffffu, ni, o);
                if (ov > nv || (ov == nv && oi < ni)) { nv = ov; ni = oi; }
            }
            if (lane == 0) { wmax[w] = nv; warg[w] = ni; }
        }
        __syncthreads();
    }
}

// =============================================================================
// K4b: init candidate outputs with dense values; flag decision-critical ones
// (label margin uses MARGIN_LBL; pairwise overall gaps use MARGIN_OVR)
// =============================================================================
__global__ __launch_bounds__(NCAND) void k4b_flag()
{
    __shared__ float ov[NCAND];
    __shared__ int   fl[NCAND];
    int b = blockIdx.x, i = threadIdx.x;
    int cand = g_cand_idx[b*NCAND + i];
    int row  = b*NPAIR + cand;
    float o  = g_overall[row];
    ov[i] = o;
    __syncthreads();

    int f = (g_margin[row] < MARGIN_LBL) ? 1 : 0;
    for (int j = 0; j < NCAND; j++)
        if (j != i && fabsf(o - ov[j]) < MARGIN_OVR) f = 1;
    fl[i] = f;

    g_cand_ovr [b*NCAND + i] = (double)o;
    g_cand_prob[b*NCAND + i] = (double)g_predprob[row];
    g_cand_lab [b*NCAND + i] = g_predlab[row];
    __syncthreads();

    if (i == 0) {
        int n = 0;
        for (int j = 0; j < NCAND; j++)
            if (fl[j]) g_fix_list[b*NCAND + (n++)] = j;
        g_fix_cnt[b] = n;
    }
}

// =============================================================================
// K5: compensated-fp32 exact partial h — FLAGGED candidates only
// =============================================================================
#define CPB 4
__global__ __launch_bounds__(256) void k5_repair_h(const float* __restrict__ inst,
                                                   const float* __restrict__ phrase,
                                                   const float* __restrict__ W1,
                                                   const int*   __restrict__ connect,
                                                   const int*   __restrict__ pidx)
{
    __shared__ float sf[CPB][1536];
    int ks = blockIdx.x;
    int g  = blockIdx.y;
    int b  = blockIdx.z;
    int tid = threadIdx.x;
    int k0 = ks * 1536;

    int cnt = g_fix_cnt[b];
    if (g * CPB >= cnt) return;
    int slots[CPB];

    #pragma unroll 1
    for (int c = 0; c < CPB; c++) {
        int jj = g*CPB + c; if (jj > cnt - 1) jj = cnt - 1;
        int slot = b*NCAND + g_fix_list[b*NCAND + jj];
        slots[c] = slot;
        int p  = g_cand_idx[slot];
        int si = connect[(size_t)b*2*NPAIR + p];
        int oi = connect[(size_t)b*2*NPAIR + NPAIR + p];
        int ph = pidx[b*NPAIR + p];
        const float* s0 = inst   + ((size_t)b*NINST + si)*1024;
        const float* s1 = inst   + ((size_t)b*NINST + oi)*1024;
        const float* s2 = phrase + ((size_t)b*NPAIR + ph)*1024;
        for (int k = tid; k < 1536; k += 256) {
            int f = k0 + k;
            float v;
            if (f < 1024)       v = s0[f];
            else if (f < 2048)  v = s1[f - 1024];
            else                v = s2[f - 2048];
            sf[c][k] = v;
        }
    }
    __syncthreads();

    float s[CPB][4] = {};
    float comp[CPB][4] = {};
    const float* wcol = W1 + (size_t)k0 * 1024 + tid * 4;
    #pragma unroll 2
    for (int k = 0; k < 1536; k++) {
        float4 w = *(const float4*)(wcol + (size_t)k * 1024);
        float wv[4] = {w.x, w.y, w.z, w.w};
        #pragma unroll
        for (int c = 0; c < CPB; c++) {
            float f = sf[c][k];
            #pragma unroll
            for (int j = 0; j < 4; j++) {
                float p  = __fmul_rn(f, wv[j]);
                float e  = __fmaf_rn(f, wv[j], -p);
                float t  = __fadd_rn(s[c][j], p);
                float z  = __fsub_rn(t, s[c][j]);
                float e2 = __fadd_rn(__fsub_rn(s[c][j], __fsub_rn(t, z)),
                                     __fsub_rn(p, z));
                comp[c][j] = __fadd_rn(comp[c][j], __fadd_rn(e2, e));
                s[c][j] = t;
            }
        }
    }
    float* outs = g_hs[ks];
    float* outc = g_hc[ks];
    #pragma unroll
    for (int c = 0; c < CPB; c++) {
        int slot = slots[c];
        *(float4*)(outs + (size_t)slot*1024 + tid*4) =
            make_float4(s[c][0], s[c][1], s[c][2], s[c][3]);
        *(float4*)(outc + (size_t)slot*1024 + tid*4) =
            make_float4(comp[c][0], comp[c][1], comp[c][2], comp[c][3]);
    }
}

// =============================================================================
// K6: exact decisions — FLAGGED candidates only
// =============================================================================
__global__ __launch_bounds__(64) void k6_decide(const float* __restrict__ W2,
                                                const float* __restrict__ b2,
                                                const float* __restrict__ b1,
                                                const float* __restrict__ scores,
                                                const int*   __restrict__ connect)
{
    __shared__ double sh[1024];
    __shared__ double slog[NCLS];
    int gid = blockIdx.x;
    int b = gid >> 7, j = gid & (NCAND - 1);
    if (j >= g_fix_cnt[b]) return;
    int slot = b*NCAND + g_fix_list[b*NCAND + j];
    int tid = threadIdx.x;
    size_t base = (size_t)slot * 1024;
    for (int k = tid; k < 1024; k += 64) {
        double v = ((double)g_hs[0][base + k] + (double)g_hc[0][base + k])
                 + ((double)g_hs[1][base + k] + (double)g_hc[1][base + k])
                 + (double)b1[k];
        v = v > 0.0 ? v : 0.01 * v;
        sh[k] = v;
    }
    __syncthreads();

    if (tid < NCLS) {
        double acc = 0.0;
        #pragma unroll 8
        for (int k = 0; k < 1024; k++)
            acc = fma(sh[k], (double)W2[(size_t)k*NCLS + tid], acc);
        slog[tid] = acc + (double)b2[tid];
    }
    __syncthreads();

    if (tid == 0) {
        double m = slog[0];
        for (int c = 1; c < NCLS; c++) m = slog[c] > m ? slog[c] : m;
        double e[NCLS]; double ssum = 0.0;
        for (int c = 0; c < NCLS; c++) { e[c] = exp(slog[c] - m); ssum += e[c]; }
        double best = 0.0; int bl = 0;
        for (int c = 1; c < NCLS; c++) {
            double pr = e[c] / ssum;
            if (pr > best) { best = pr; bl = c; }
        }
        int p = g_cand_idx[slot];
        int si = connect[(size_t)b*2*NPAIR + p];
        int oi = connect[(size_t)b*2*NPAIR + NPAIR + p];
        double ov = best * (double)scores[b*NINST + si] * (double)scores[b*NINST + oi];
        g_cand_ovr[slot]  = ov;
        g_cand_prob[slot] = best;
        g_cand_lab[slot]  = bl;
    }
}

// =============================================================================
// K7: final top-100 per batch over NCAND candidates
// =============================================================================
__global__ __launch_bounds__(128) void k7_final(float* __restrict__ outbase)
{
    __shared__ double v[NCAND];
    __shared__ int    pix[NCAND];
    int b = blockIdx.x, tid = threadIdx.x;
    v[tid]   = g_cand_ovr[b*NCAND + tid];
    pix[tid] = g_cand_idx[b*NCAND + tid];
    __syncthreads();

    if (tid == 0) {
        float* out_lab  = outbase;
        float* out_prob = outbase + 800;
        float* out_val  = outbase + 1600;
        float* out_idx  = outbase + 2400;
        for (int t = 0; t < 100; t++) {
            double bv = -1.0; int bj = 0; int bidx = 0x7fffffff;
            for (int j = 0; j < NCAND; j++) {
                double val = v[j]; int ix = pix[j];
                if (val > bv || (val == bv && ix < bidx)) { bv = val; bj = j; bidx = ix; }
            }
            int slot2 = b*NCAND + bj;
            out_val [b*100 + t] = (float)bv;
            out_idx [b*100 + t] = (float)bidx;
            out_lab [b*100 + t] = (float)g_cand_lab[slot2];
            out_prob[b*100 + t] = (float)g_cand_prob[slot2];
            v[bj] = -2.0;
        }
    }
}

// =============================================================================
extern "C" void kernel_launch(void* const* d_in, const int* in_sizes, int n_in,
                              void* d_out, int out_size)
{
    const float* inst    = (const float*)d_in[0];
    const float* phrase  = (const float*)d_in[1];
    const float* scores  = (const float*)d_in[2];
    const float* W1      = (const float*)d_in[3];
    const float* b1      = (const float*)d_in[4];
    const float* W2      = (const float*)d_in[5];
    const float* b2      = (const float*)d_in[6];
    const int*   connect = (const int*)d_in[7];
    const int*   pidx    = (const int*)d_in[8];

    float* out        = (float*)d_out;
    float* out_logits = out;
    float* out_probs  = out + (size_t)BATCH*NPAIR*NCLS;
    float* out_top    = out + (size_t)2*BATCH*NPAIR*NCLS;

    cudaFuncSetAttribute(k2_mma, cudaFuncAttributeMaxDynamicSharedMemorySize, K2_SMEM);

    kprep_all<<<1088, 256>>>(W1, W2, b2, out_logits);
    kprep_a<<<NROWS, 256>>>(phrase, pidx);
    k1_instproj<<<dim3(32, 13), 256>>>(inst, W1);
    k2_mma<<<dim3(8, 78, BATCH), 256, K2_SMEM>>>(b1, connect, out_logits);
    k3b_softmax<<<(NROWS + 255) / 256, 256>>>(out_logits, scores, connect, out_probs);
    k4_select<<<BATCH, 1024>>>();
    k4b_flag<<<BATCH, NCAND>>>();
    k5_repair_h<<<dim3(2, 32, BATCH), 256>>>(inst, phrase, W1, connect, pidx);
    k6_decide<<<BATCH*NCAND, 64>>>(W2, b2, b1, scores, connect);
    k7_final<<<BATCH, 128>>>(out_top);
}